// round 2
// baseline (speedup 1.0000x reference)
#include <cuda_runtime.h>
#include <cstdint>

#define BS   4
#define LSEQ 2048
#define CIN  32
#define COUT 32
#define HID  64
#define KTAPS 8
#define NPOS (BS*LSEQ)      /* 8192 */
#define JDIM 2112           /* 2048 outer + 32 fsum + 32 feat */
#define EPSV 1e-5f

#define PTILE 128
#define JSPLIT 11
#define JCH 192             /* JDIM / JSPLIT = 3 chunks of 64 */

// Scratch (no allocations allowed): ~70 MB total
__device__ float g_Z[(size_t)NPOS * JDIM];   // 69.2 MB
__device__ float g_Wv[JDIM * COUT];          // 270 KB
__device__ float g_out[NPOS * COUT];         // 1 MB (pre-norm output)
__device__ float g_S[64];                    // per-channel sum / sumsq

// ---------------------------------------------------------------------------
__global__ void k_init() {
    int idx = blockIdx.x * blockDim.x + threadIdx.x;
    if (idx < NPOS * COUT) g_out[idx] = 0.f;
    if (idx < 64) g_S[idx] = 0.f;
}

// Repack weights: Wv[j][o]
//   j in [0,2048):  j = c*64+h  ->  W2[h, c*32+o]
//   j in [2048,2080): c = j-2048 -> b2[c*32+o]
//   j in [2080,2112): c = j-2080 -> W_skip[c][o]
__global__ void k_prep(const float* __restrict__ W2, const float* __restrict__ b2,
                       const float* __restrict__ Wskip) {
    int idx = blockIdx.x * blockDim.x + threadIdx.x;
    if (idx >= JDIM * COUT) return;
    int j = idx >> 5, o = idx & 31;
    float v;
    if (j < 2048) {
        int c = j >> 6, h = j & 63;
        v = W2[h * (CIN * COUT) + c * COUT + o];
    } else if (j < 2080) {
        int c = j - 2048;
        v = b2[c * COUT + o];
    } else {
        int c = j - 2080;
        v = Wskip[c * COUT + o];
    }
    g_Wv[idx] = v;
}

// ---------------------------------------------------------------------------
// Stage 1: one warp per (b,t) position. Lane = input channel c (and h-pair).
// Builds Z[pos, c*64+h] = sum_k h[k][h] * f[k][c], plus fsum and raw feat cols.
__global__ __launch_bounds__(256) void k_stage1(const float* __restrict__ times,
                                                const float* __restrict__ feat,
                                                const unsigned char* __restrict__ npm,
                                                const float* __restrict__ W1,
                                                const float* __restrict__ b1) {
    __shared__ float W1s[CIN * HID];
    __shared__ float b1s[HID];
    int tid = threadIdx.x;
    for (int i = tid; i < CIN * HID; i += 256) W1s[i] = W1[i];
    if (tid < HID) b1s[tid] = b1[tid];
    __syncthreads();

    int lane = tid & 31;
    int pos = blockIdx.x * 8 + (tid >> 5);
    int b = pos >> 11, t = pos & (LSEQ - 1);

    // mask dtype detection: element 1 is always true (lengths >= 1024).
    // u8 layout -> byte[1]!=0 ; int32/float layout -> byte[1]==0.
    bool u8 = (npm[1] != 0);
    const int* npm32 = (const int*)npm;

    float z0[CIN], z1[CIN];
#pragma unroll
    for (int c = 0; c < CIN; c++) { z0[c] = 0.f; z1[c] = 0.f; }
    float fs = 0.f;

    // inv POS_VEC: 10000^(-(lane/2)/16) ; log2(10000)/16 = 0.83048202...
    float invp = exp2f(-(float)(lane >> 1) * 0.8304820237218407f);

    bool mt = u8 ? (npm[b * LSEQ + t] != 0) : (npm32[b * LSEQ + t] != 0);
    float tt = times[b * LSEQ + t];

    if (mt) {
        for (int k = 0; k < KTAPS; k++) {
            int idx = t - (KTAPS - 1) + k;
            if (idx < 0) continue;                      // warp-uniform
            bool mk = u8 ? (npm[b * LSEQ + idx] != 0) : (npm32[b * LSEQ + idx] != 0);
            if (!mk) continue;                          // warp-uniform
            float dt = tt - times[b * LSEQ + idx];
            float f = feat[(size_t)(b * LSEQ + idx) * CIN + lane];
            fs += f;
            float r = dt * invp;
            float te = (lane & 1) ? __cosf(r) : __sinf(r);
            // h_j = relu(sum_c te_c * W1[c][j] + b1[j]); lane owns j=lane, lane+32
            float a0 = b1s[lane], a1 = b1s[lane + 32];
#pragma unroll
            for (int c = 0; c < CIN; c++) {
                float tv = __shfl_sync(0xffffffffu, te, c);
                a0 += tv * W1s[c * HID + lane];
                a1 += tv * W1s[c * HID + 32 + lane];
            }
            a0 = fmaxf(a0, 0.f);
            a1 = fmaxf(a1, 0.f);
            // rank-1 accumulate: z[h][c] += h_h * f_c  (broadcast f over lanes)
#pragma unroll
            for (int c = 0; c < CIN; c++) {
                float fv = __shfl_sync(0xffffffffu, f, c);
                z0[c] += a0 * fv;
                z1[c] += a1 * fv;
            }
        }
    }

    float* zr = g_Z + (size_t)pos * JDIM;
#pragma unroll
    for (int c = 0; c < CIN; c++) {
        zr[c * 64 + lane]      = z0[c];   // coalesced across lanes
        zr[c * 64 + 32 + lane] = z1[c];
    }
    zr[2048 + lane] = fs;
    zr[2080 + lane] = feat[(size_t)(b * LSEQ + t) * CIN + lane];
}

// ---------------------------------------------------------------------------
// Stage 2: GEMM  g_out[8192,32] += Z[8192, jrange] @ Wv[jrange, 32]
// CTA: 128 positions x 32 outputs, 256 threads, 4x4 register tile.
// Grid.y splits the inner dim 11 ways (atomics combine the partials).
__global__ __launch_bounds__(256) void k_stage2() {
    __shared__ float Zs[PTILE * 65];   // pad 65 -> conflict-free p-strided reads
    __shared__ float Ws[64 * 32];
    int tid = threadIdx.x;
    int og = tid & 7, tp = tid >> 3;   // og: 8 groups of 4 outs, tp: 32 groups of 4 pos
    int ob = og * 4;                   // float4-aligned
    int posBase = blockIdx.x * PTILE;
    int jBase = blockIdx.y * JCH;

    float acc[4][4];
#pragma unroll
    for (int i = 0; i < 4; i++)
#pragma unroll
        for (int j = 0; j < 4; j++) acc[i][j] = 0.f;

    for (int cb = 0; cb < JCH; cb += 64) {
        int jb = jBase + cb;
        // stage Wv chunk: 64x32 floats, float4 loads/stores
        for (int i = tid; i < 64 * 8; i += 256) {
            *(float4*)(Ws + i * 4) = *(const float4*)(g_Wv + jb * 32 + i * 4);
        }
        // stage Z chunk: 128 pos x 64 j, float4 global loads, scalar smem stores
        for (int idx = tid; idx < PTILE * 16; idx += 256) {
            int row = idx >> 4, q = idx & 15;
            float4 v = *(const float4*)(g_Z + (size_t)(posBase + row) * JDIM + jb + q * 4);
            float* d = Zs + row * 65 + q * 4;
            d[0] = v.x; d[1] = v.y; d[2] = v.z; d[3] = v.w;
        }
        __syncthreads();
#pragma unroll 16
        for (int x = 0; x < 64; x++) {
            float4 wv = *(const float4*)(Ws + x * 32 + ob);
            float zv0 = Zs[(tp * 4 + 0) * 65 + x];
            float zv1 = Zs[(tp * 4 + 1) * 65 + x];
            float zv2 = Zs[(tp * 4 + 2) * 65 + x];
            float zv3 = Zs[(tp * 4 + 3) * 65 + x];
            acc[0][0] += zv0 * wv.x; acc[0][1] += zv0 * wv.y;
            acc[0][2] += zv0 * wv.z; acc[0][3] += zv0 * wv.w;
            acc[1][0] += zv1 * wv.x; acc[1][1] += zv1 * wv.y;
            acc[1][2] += zv1 * wv.z; acc[1][3] += zv1 * wv.w;
            acc[2][0] += zv2 * wv.x; acc[2][1] += zv2 * wv.y;
            acc[2][2] += zv2 * wv.z; acc[2][3] += zv2 * wv.w;
            acc[3][0] += zv3 * wv.x; acc[3][1] += zv3 * wv.y;
            acc[3][2] += zv3 * wv.z; acc[3][3] += zv3 * wv.w;
        }
        __syncthreads();
    }
#pragma unroll
    for (int i = 0; i < 4; i++) {
        int p = posBase + tp * 4 + i;
#pragma unroll
        for (int j = 0; j < 4; j++) atomicAdd(&g_out[p * 32 + ob + j], acc[i][j]);
    }
}

// ---------------------------------------------------------------------------
// Stage 3a: per-channel sum / sumsq over all 8192 positions
__global__ __launch_bounds__(256) void k_stats() {
    __shared__ float ss[256], sq[256];
    int tid = threadIdx.x;
    int base = blockIdx.x * 4096;
    float s = 0.f, q = 0.f;
    for (int i = base + tid; i < base + 4096; i += 256) {
        float v = g_out[i];
        s += v;
        q += v * v;
    }
    ss[tid] = s; sq[tid] = q;
    __syncthreads();
    if (tid < 32) {
        for (int w = 1; w < 8; w++) { s += ss[w * 32 + tid]; q += sq[w * 32 + tid]; }
        atomicAdd(&g_S[tid], s);
        atomicAdd(&g_S[32 + tid], q);
    }
}

// Stage 3b: normalize (b_skip cancels: constant per-channel shift)
__global__ void k_norm(const float* __restrict__ gamma, const float* __restrict__ beta,
                       float* __restrict__ out) {
    int idx = blockIdx.x * blockDim.x + threadIdx.x;
    if (idx >= NPOS * COUT) return;
    int o = idx & 31;
    float mean = g_S[o] * (1.f / NPOS);
    float var = g_S[32 + o] * (1.f / NPOS) - mean * mean;
    out[idx] = gamma[o] * (g_out[idx] - mean) * rsqrtf(var + EPSV) + beta[o];
}

// ---------------------------------------------------------------------------
extern "C" void kernel_launch(void* const* d_in, const int* in_sizes, int n_in,
                              void* d_out, int out_size) {
    const float* times = (const float*)d_in[0];
    const float* feat  = (const float*)d_in[1];
    const unsigned char* npm = (const unsigned char*)d_in[2];
    const float* W1    = (const float*)d_in[3];
    const float* b1    = (const float*)d_in[4];
    const float* W2    = (const float*)d_in[5];
    const float* b2    = (const float*)d_in[6];
    const float* Wskip = (const float*)d_in[7];
    /* d_in[8] = b_skip: mathematically cancels in layernorm */
    const float* gamma = (const float*)d_in[9];
    const float* beta  = (const float*)d_in[10];

    k_init<<<(NPOS * COUT + 255) / 256, 256>>>();
    k_prep<<<(JDIM * COUT + 255) / 256, 256>>>(W2, b2, Wskip);
    k_stage1<<<NPOS / 8, 256>>>(times, feat, npm, W1, b1);
    dim3 g2(NPOS / PTILE, JSPLIT);
    k_stage2<<<g2, 256>>>();
    k_stats<<<64, 256>>>();
    k_norm<<<(NPOS * COUT + 255) / 256, 256>>>(gamma, beta, (float*)d_out);
}

// round 3
// speedup vs baseline: 1.5010x; 1.5010x over previous
#include <cuda_runtime.h>
#include <cstdint>

#define BS   4
#define LSEQ 2048
#define CIN  32
#define COUT 32
#define HID  64
#define KTAPS 8
#define NPOS (BS*LSEQ)      /* 8192 */
#define JDIM 2112           /* 2048 outer + 32 fsum + 32 feat */
#define EPSV 1e-5f

#define PTILE 128
#define JSPLIT 11
#define JCH 192             /* JDIM / JSPLIT = 3 chunks of 64 */

// Scratch (no allocations allowed)
__device__ float g_Z[(size_t)NPOS * JDIM];              // 69.2 MB
__device__ float g_Wv[JDIM * COUT];                     // 270 KB
__device__ float g_part[(size_t)JSPLIT * NPOS * COUT];  // 11.5 MB partials
__device__ float g_out[NPOS * COUT];                    // 1 MB (pre-norm)
__device__ float g_S[64];                               // channel sum / sumsq

// ---------------------------------------------------------------------------
__global__ void k_init() {
    int idx = blockIdx.x * blockDim.x + threadIdx.x;
    if (idx < 64) g_S[idx] = 0.f;
}

// Repack weights: Wv[j][o]
//   j in [0,2048):  j = c*64+h  ->  W2[h, c*32+o]
//   j in [2048,2080): c = j-2048 -> b2[c*32+o]
//   j in [2080,2112): c = j-2080 -> W_skip[c][o]
__global__ void k_prep(const float* __restrict__ W2, const float* __restrict__ b2,
                       const float* __restrict__ Wskip) {
    int idx = blockIdx.x * blockDim.x + threadIdx.x;
    if (idx >= JDIM * COUT) return;
    int j = idx >> 5, o = idx & 31;
    float v;
    if (j < 2048) {
        int c = j >> 6, h = j & 63;
        v = W2[h * (CIN * COUT) + c * COUT + o];
    } else if (j < 2080) {
        int c = j - 2048;
        v = b2[c * COUT + o];
    } else {
        int c = j - 2080;
        v = Wskip[c * COUT + o];
    }
    g_Wv[idx] = v;
}

// ---------------------------------------------------------------------------
// Stage 1: one warp per (b,t) position. Lane = input channel c (and h-pair).
// Builds Z[pos, c*64+h] = sum_k h[k][h] * f[k][c], plus fsum and raw feat cols.
__global__ __launch_bounds__(256) void k_stage1(const float* __restrict__ times,
                                                const float* __restrict__ feat,
                                                const unsigned char* __restrict__ npm,
                                                const float* __restrict__ W1,
                                                const float* __restrict__ b1) {
    __shared__ float W1s[CIN * HID];
    __shared__ float b1s[HID];
    int tid = threadIdx.x;
    for (int i = tid; i < CIN * HID; i += 256) W1s[i] = W1[i];
    if (tid < HID) b1s[tid] = b1[tid];
    __syncthreads();

    int lane = tid & 31;
    int pos = blockIdx.x * 8 + (tid >> 5);
    int b = pos >> 11, t = pos & (LSEQ - 1);

    // mask dtype detection: element 1 is always true (lengths >= 1024).
    // u8 layout -> byte[1]!=0 ; int32/float layout -> byte[1]==0.
    bool u8 = (npm[1] != 0);
    const int* npm32 = (const int*)npm;

    float z0[CIN], z1[CIN];
#pragma unroll
    for (int c = 0; c < CIN; c++) { z0[c] = 0.f; z1[c] = 0.f; }
    float fs = 0.f;

    // inv POS_VEC: 10000^(-(lane/2)/16) ; log2(10000)/16 = 0.83048202...
    float invp = exp2f(-(float)(lane >> 1) * 0.8304820237218407f);

    bool mt = u8 ? (npm[b * LSEQ + t] != 0) : (npm32[b * LSEQ + t] != 0);
    float tt = times[b * LSEQ + t];

    if (mt) {
        for (int k = 0; k < KTAPS; k++) {
            int idx = t - (KTAPS - 1) + k;
            if (idx < 0) continue;                      // warp-uniform
            bool mk = u8 ? (npm[b * LSEQ + idx] != 0) : (npm32[b * LSEQ + idx] != 0);
            if (!mk) continue;                          // warp-uniform
            float dt = tt - times[b * LSEQ + idx];
            float f = feat[(size_t)(b * LSEQ + idx) * CIN + lane];
            fs += f;
            float r = dt * invp;
            float te = (lane & 1) ? __cosf(r) : __sinf(r);
            // h_j = relu(sum_c te_c * W1[c][j] + b1[j]); lane owns j=lane, lane+32
            float a0 = b1s[lane], a1 = b1s[lane + 32];
#pragma unroll
            for (int c = 0; c < CIN; c++) {
                float tv = __shfl_sync(0xffffffffu, te, c);
                a0 += tv * W1s[c * HID + lane];
                a1 += tv * W1s[c * HID + 32 + lane];
            }
            a0 = fmaxf(a0, 0.f);
            a1 = fmaxf(a1, 0.f);
            // rank-1 accumulate: z[h][c] += h_h * f_c  (broadcast f over lanes)
#pragma unroll
            for (int c = 0; c < CIN; c++) {
                float fv = __shfl_sync(0xffffffffu, f, c);
                z0[c] += a0 * fv;
                z1[c] += a1 * fv;
            }
        }
    }

    float* zr = g_Z + (size_t)pos * JDIM;
#pragma unroll
    for (int c = 0; c < CIN; c++) {
        zr[c * 64 + lane]      = z0[c];   // coalesced across lanes
        zr[c * 64 + 32 + lane] = z1[c];
    }
    zr[2048 + lane] = fs;
    zr[2080 + lane] = feat[(size_t)(b * LSEQ + t) * CIN + lane];
}

// ---------------------------------------------------------------------------
// Stage 2: GEMM partials  g_part[s][8192,32] = Z[8192, jrange_s] @ Wv[jrange_s, 32]
// CTA: 128 positions x 32 outputs, 128 threads, 4 pos x 8 out register tile.
// 6 LDS per 32 FMA. No atomics: coalesced float4 partial stores.
__global__ __launch_bounds__(128) void k_stage2() {
    __shared__ float Zs[PTILE * 65];   // pad 65 -> conflict-free p-strided reads
    __shared__ float Ws[64 * 32];
    int tid = threadIdx.x;
    int og = tid & 3, tp = tid >> 2;   // og: 4 groups of 8 outs, tp: 32 groups of 4 pos
    int ob = og * 8;
    int posBase = blockIdx.x * PTILE;
    int jBase = blockIdx.y * JCH;

    float acc[4][8];
#pragma unroll
    for (int i = 0; i < 4; i++)
#pragma unroll
        for (int j = 0; j < 8; j++) acc[i][j] = 0.f;

    for (int cb = 0; cb < JCH; cb += 64) {
        int jb = jBase + cb;
        // stage Wv chunk: 64x32 floats, float4
        for (int i = tid; i < 64 * 8; i += 128) {
            *(float4*)(Ws + i * 4) = *(const float4*)(g_Wv + jb * 32 + i * 4);
        }
        // stage Z chunk: 128 pos x 64 j, float4 global loads
        for (int idx = tid; idx < PTILE * 16; idx += 128) {
            int row = idx >> 4, q = idx & 15;
            float4 v = *(const float4*)(g_Z + (size_t)(posBase + row) * JDIM + jb + q * 4);
            float* d = Zs + row * 65 + q * 4;
            d[0] = v.x; d[1] = v.y; d[2] = v.z; d[3] = v.w;
        }
        __syncthreads();
#pragma unroll 16
        for (int x = 0; x < 64; x++) {
            float4 w0 = *(const float4*)(Ws + x * 32 + ob);
            float4 w1 = *(const float4*)(Ws + x * 32 + ob + 4);
            float z0 = Zs[(tp * 4 + 0) * 65 + x];
            float z1 = Zs[(tp * 4 + 1) * 65 + x];
            float z2 = Zs[(tp * 4 + 2) * 65 + x];
            float z3 = Zs[(tp * 4 + 3) * 65 + x];
            acc[0][0] += z0 * w0.x; acc[0][1] += z0 * w0.y;
            acc[0][2] += z0 * w0.z; acc[0][3] += z0 * w0.w;
            acc[0][4] += z0 * w1.x; acc[0][5] += z0 * w1.y;
            acc[0][6] += z0 * w1.z; acc[0][7] += z0 * w1.w;
            acc[1][0] += z1 * w0.x; acc[1][1] += z1 * w0.y;
            acc[1][2] += z1 * w0.z; acc[1][3] += z1 * w0.w;
            acc[1][4] += z1 * w1.x; acc[1][5] += z1 * w1.y;
            acc[1][6] += z1 * w1.z; acc[1][7] += z1 * w1.w;
            acc[2][0] += z2 * w0.x; acc[2][1] += z2 * w0.y;
            acc[2][2] += z2 * w0.z; acc[2][3] += z2 * w0.w;
            acc[2][4] += z2 * w1.x; acc[2][5] += z2 * w1.y;
            acc[2][6] += z2 * w1.z; acc[2][7] += z2 * w1.w;
            acc[3][0] += z3 * w0.x; acc[3][1] += z3 * w0.y;
            acc[3][2] += z3 * w0.z; acc[3][3] += z3 * w0.w;
            acc[3][4] += z3 * w1.x; acc[3][5] += z3 * w1.y;
            acc[3][6] += z3 * w1.z; acc[3][7] += z3 * w1.w;
        }
        __syncthreads();
    }
    float* dst = g_part + (size_t)blockIdx.y * (NPOS * COUT);
#pragma unroll
    for (int i = 0; i < 4; i++) {
        int p = posBase + tp * 4 + i;
        *(float4*)(dst + p * 32 + ob) =
            make_float4(acc[i][0], acc[i][1], acc[i][2], acc[i][3]);
        *(float4*)(dst + p * 32 + ob + 4) =
            make_float4(acc[i][4], acc[i][5], acc[i][6], acc[i][7]);
    }
}

// ---------------------------------------------------------------------------
// Stage 3a: reduce JSPLIT partials -> g_out, and per-channel sum / sumsq
__global__ __launch_bounds__(256) void k_stats() {
    __shared__ float ss[256], sq[256];
    int tid = threadIdx.x;
    int base = blockIdx.x * 4096;
    float s = 0.f, q = 0.f;
    for (int i = base + tid; i < base + 4096; i += 256) {
        float v = 0.f;
#pragma unroll
        for (int sp = 0; sp < JSPLIT; sp++) v += g_part[(size_t)sp * (NPOS * COUT) + i];
        g_out[i] = v;
        s += v;
        q += v * v;
    }
    ss[tid] = s; sq[tid] = q;
    __syncthreads();
    if (tid < 32) {
        for (int w = 1; w < 8; w++) { s += ss[w * 32 + tid]; q += sq[w * 32 + tid]; }
        atomicAdd(&g_S[tid], s);
        atomicAdd(&g_S[32 + tid], q);
    }
}

// Stage 3b: normalize (b_skip cancels: constant per-channel shift)
__global__ void k_norm(const float* __restrict__ gamma, const float* __restrict__ beta,
                       float* __restrict__ out) {
    int idx = blockIdx.x * blockDim.x + threadIdx.x;
    if (idx >= NPOS * COUT) return;
    int o = idx & 31;
    float mean = g_S[o] * (1.f / NPOS);
    float var = g_S[32 + o] * (1.f / NPOS) - mean * mean;
    out[idx] = gamma[o] * (g_out[idx] - mean) * rsqrtf(var + EPSV) + beta[o];
}

// ---------------------------------------------------------------------------
extern "C" void kernel_launch(void* const* d_in, const int* in_sizes, int n_in,
                              void* d_out, int out_size) {
    const float* times = (const float*)d_in[0];
    const float* feat  = (const float*)d_in[1];
    const unsigned char* npm = (const unsigned char*)d_in[2];
    const float* W1    = (const float*)d_in[3];
    const float* b1    = (const float*)d_in[4];
    const float* W2    = (const float*)d_in[5];
    const float* b2    = (const float*)d_in[6];
    const float* Wskip = (const float*)d_in[7];
    /* d_in[8] = b_skip: mathematically cancels in layernorm */
    const float* gamma = (const float*)d_in[9];
    const float* beta  = (const float*)d_in[10];

    k_init<<<1, 64>>>();
    k_prep<<<(JDIM * COUT + 255) / 256, 256>>>(W2, b2, Wskip);
    k_stage1<<<NPOS / 8, 256>>>(times, feat, npm, W1, b1);
    dim3 g2(NPOS / PTILE, JSPLIT);
    k_stage2<<<g2, 128>>>();
    k_stats<<<64, 256>>>();
    k_norm<<<(NPOS * COUT + 255) / 256, 256>>>(gamma, beta, (float*)d_out);
}

// round 8
// speedup vs baseline: 1.5772x; 1.0508x over previous
#include <cuda_runtime.h>
#include <cstdint>

typedef unsigned long long ull;

#define BS   4
#define LSEQ 2048
#define CIN  32
#define COUT 32
#define HID  64
#define KTAPS 8
#define NPOS (BS*LSEQ)      /* 8192 */
#define JDIM 2112           /* 2048 outer + 32 fsum + 32 feat */
#define EPSV 1e-5f

#define PTILE 128
#define JSPLIT 11
#define JCH 192             /* JDIM / JSPLIT */
#define JCHUNK 32
#define NCHUNK (JCH / JCHUNK)   /* 6 */
#define ZPAD 33

// Scratch (no allocations allowed)
__device__ float g_Z[(size_t)NPOS * JDIM];              // 69.2 MB
__device__ float g_Wv[JDIM * COUT];                     // 270 KB
__device__ float g_part[(size_t)JSPLIT * NPOS * COUT];  // 11.5 MB partials
__device__ float g_out[NPOS * COUT];                    // 1 MB (pre-norm)
__device__ float g_S[64];                               // channel sum / sumsq

// ---- packed fp32 helpers (sm_103a f32x2 pipe) ------------------------------
__device__ __forceinline__ ull pk(float lo, float hi) {
    ull r; asm("mov.b64 %0, {%1, %2};" : "=l"(r) : "f"(lo), "f"(hi)); return r;
}
__device__ __forceinline__ void upk(ull v, float& lo, float& hi) {
    asm("mov.b64 {%0, %1}, %2;" : "=f"(lo), "=f"(hi) : "l"(v));
}
__device__ __forceinline__ void fma2(ull& d, ull a, ull b) {
    asm("fma.rn.f32x2 %0, %1, %2, %0;" : "+l"(d) : "l"(a), "l"(b));
}

// ---------------------------------------------------------------------------
__global__ void k_init() {
    int idx = blockIdx.x * blockDim.x + threadIdx.x;
    if (idx < 64) g_S[idx] = 0.f;
}

// Repack weights: Wv[j][o]
//   j in [0,2048):  j = c*64+h  ->  W2[h, c*32+o]
//   j in [2048,2080): c = j-2048 -> b2[c*32+o]
//   j in [2080,2112): c = j-2080 -> W_skip[c][o]
__global__ void k_prep(const float* __restrict__ W2, const float* __restrict__ b2,
                       const float* __restrict__ Wskip) {
    int idx = blockIdx.x * blockDim.x + threadIdx.x;
    if (idx >= JDIM * COUT) return;
    int j = idx >> 5, o = idx & 31;
    float v;
    if (j < 2048) {
        int c = j >> 6, h = j & 63;
        v = W2[h * (CIN * COUT) + c * COUT + o];
    } else if (j < 2080) {
        int c = j - 2048;
        v = b2[c * COUT + o];
    } else {
        int c = j - 2080;
        v = Wskip[c * COUT + o];
    }
    g_Wv[idx] = v;
}

// ---------------------------------------------------------------------------
// Stage 1: one warp per (b,t) position. Lane = input channel c (and h-pair).
// Builds Z[pos, c*64+h] = sum_k h[k][h] * f[k][c], plus fsum and raw feat cols.
// f32x2: h-pair (j, j+32) computed as one packed value; z-pairs likewise.
__global__ __launch_bounds__(256) void k_stage1(const float* __restrict__ times,
                                                const float* __restrict__ feat,
                                                const unsigned char* __restrict__ npm,
                                                const float* __restrict__ W1,
                                                const float* __restrict__ b1) {
    __shared__ ull W1p[CIN * 32];   // [c][j] = (W1[c][j], W1[c][j+32])
    __shared__ float b1s[HID];
    int tid = threadIdx.x;
    for (int i = tid; i < CIN * 32; i += 256) {
        int c = i >> 5, j = i & 31;
        W1p[i] = pk(W1[c * HID + j], W1[c * HID + 32 + j]);
    }
    if (tid < HID) b1s[tid] = b1[tid];
    __syncthreads();

    int lane = tid & 31;
    int pos = blockIdx.x * 8 + (tid >> 5);
    int b = pos >> 11, t = pos & (LSEQ - 1);

    // mask dtype detection: element 1 is always true (lengths >= 1024).
    bool u8 = (npm[1] != 0);
    const int* npm32 = (const int*)npm;

    ull z2[CIN];                     // (z0[c], z1[c]) packed
#pragma unroll
    for (int c = 0; c < CIN; c++) z2[c] = 0ull;
    float fs = 0.f;

    // inv POS_VEC: 10000^(-(lane/2)/16) ; log2(10000)/16 = 0.83048202...
    float invp = exp2f(-(float)(lane >> 1) * 0.8304820237218407f);
    ull b1p = pk(b1s[lane], b1s[lane + 32]);

    bool mt = u8 ? (npm[b * LSEQ + t] != 0) : (npm32[b * LSEQ + t] != 0);
    float tt = times[b * LSEQ + t];

    if (mt) {
        for (int k = 0; k < KTAPS; k++) {
            int idx = t - (KTAPS - 1) + k;
            if (idx < 0) continue;                      // warp-uniform
            bool mk = u8 ? (npm[b * LSEQ + idx] != 0) : (npm32[b * LSEQ + idx] != 0);
            if (!mk) continue;                          // warp-uniform
            float dt = tt - times[b * LSEQ + idx];
            float f = feat[(size_t)(b * LSEQ + idx) * CIN + lane];
            fs += f;
            float r = dt * invp;
            float te = (lane & 1) ? __cosf(r) : __sinf(r);
            // h-pair GEMV: ap = b1p + sum_c (te_c,te_c)*(W1[c][lane],W1[c][lane+32])
            ull ap = b1p;
#pragma unroll
            for (int c = 0; c < CIN; c++) {
                float tv = __shfl_sync(0xffffffffu, te, c);
                fma2(ap, pk(tv, tv), W1p[c * 32 + lane]);
            }
            float a0, a1;
            upk(ap, a0, a1);
            a0 = fmaxf(a0, 0.f);
            a1 = fmaxf(a1, 0.f);
            ull a2 = pk(a0, a1);
            // rank-1 accumulate: (z0[c],z1[c]) += (a0,a1)*(f_c,f_c)
#pragma unroll
            for (int c = 0; c < CIN; c++) {
                float fv = __shfl_sync(0xffffffffu, f, c);
                fma2(z2[c], a2, pk(fv, fv));
            }
        }
    }

    float* zr = g_Z + (size_t)pos * JDIM;
#pragma unroll
    for (int c = 0; c < CIN; c++) {
        float z0, z1;
        upk(z2[c], z0, z1);
        zr[c * 64 + lane]      = z0;   // coalesced across lanes
        zr[c * 64 + 32 + lane] = z1;
    }
    zr[2048 + lane] = fs;
    zr[2080 + lane] = feat[(size_t)(b * LSEQ + t) * CIN + lane];
}

// ---------------------------------------------------------------------------
// Stage 2: GEMM partials  g_part[s][8192,32] = Z[8192, jrange_s] @ Wv[jrange_s, 32]
// CTA: 128 pos x 32 outs, 128 threads, 4 pos x 8 out tile via f32x2 (4x4 pair accs).
// Register-staged pipelining: LDG chunk q+1 issued before computing chunk q.
// ZPAD=33 makes STS (bank=r+4q+e) and LDS (bank=4tp+i+x) conflict-free.
__global__ __launch_bounds__(128) void k_stage2() {
    __shared__ float Zs[PTILE * ZPAD];    // 16.9 KB
    __shared__ float Ws[JCHUNK * 32];     // 4 KB
    int tid = threadIdx.x;
    int og = tid & 3, tp = tid >> 2;
    int ob = og * 8;
    int posBase = blockIdx.x * PTILE;
    int jBase = blockIdx.y * JCH;

    ull acc2[4][4];
#pragma unroll
    for (int i = 0; i < 4; i++)
#pragma unroll
        for (int p = 0; p < 4; p++) acc2[i][p] = 0ull;

    float4 vz[8], vw[2];
    auto ldg_chunk = [&](int q) {
        int j0 = jBase + q * JCHUNK;
#pragma unroll
        for (int t = 0; t < 8; t++) {
            int idx = t * 128 + tid;
            int row = idx >> 3, qd = idx & 7;
            vz[t] = *(const float4*)(g_Z + (size_t)(posBase + row) * JDIM + j0 + qd * 4);
        }
#pragma unroll
        for (int t = 0; t < 2; t++)
            vw[t] = *(const float4*)(g_Wv + j0 * 32 + (t * 128 + tid) * 4);
    };

    ldg_chunk(0);
#pragma unroll 1
    for (int q = 0; q < NCHUNK; q++) {
        __syncthreads();   // previous compute done before overwriting smem
#pragma unroll
        for (int t = 0; t < 8; t++) {
            int idx = t * 128 + tid;
            int row = idx >> 3, qd = idx & 7;
            float* d = Zs + row * ZPAD + qd * 4;
            d[0] = vz[t].x; d[1] = vz[t].y; d[2] = vz[t].z; d[3] = vz[t].w;
        }
#pragma unroll
        for (int t = 0; t < 2; t++)
            *(float4*)(Ws + (t * 128 + tid) * 4) = vw[t];
        __syncthreads();
        if (q + 1 < NCHUNK) ldg_chunk(q + 1);   // in flight during compute
#pragma unroll
        for (int x = 0; x < JCHUNK; x++) {
            ull w0 = *(const ull*)(Ws + x * 32 + ob);
            ull w1 = *(const ull*)(Ws + x * 32 + ob + 2);
            ull w2 = *(const ull*)(Ws + x * 32 + ob + 4);
            ull w3 = *(const ull*)(Ws + x * 32 + ob + 6);
#pragma unroll
            for (int i = 0; i < 4; i++) {
                float z = Zs[(tp * 4 + i) * ZPAD + x];
                ull zp = pk(z, z);
                fma2(acc2[i][0], zp, w0);
                fma2(acc2[i][1], zp, w1);
                fma2(acc2[i][2], zp, w2);
                fma2(acc2[i][3], zp, w3);
            }
        }
    }

    float* dst = g_part + (size_t)blockIdx.y * (NPOS * COUT);
#pragma unroll
    for (int i = 0; i < 4; i++) {
        int p = posBase + tp * 4 + i;
        float a, b, c, d, e, f, g, h;
        upk(acc2[i][0], a, b); upk(acc2[i][1], c, d);
        upk(acc2[i][2], e, f); upk(acc2[i][3], g, h);
        *(float4*)(dst + p * 32 + ob)     = make_float4(a, b, c, d);
        *(float4*)(dst + p * 32 + ob + 4) = make_float4(e, f, g, h);
    }
}

// ---------------------------------------------------------------------------
// Stage 3a: reduce JSPLIT partials -> g_out, and per-channel sum / sumsq
__global__ __launch_bounds__(256) void k_stats() {
    __shared__ float ss[256], sq[256];
    int tid = threadIdx.x;
    int base = blockIdx.x * 4096;
    float s = 0.f, q = 0.f;
    for (int i = base + tid; i < base + 4096; i += 256) {
        float v = 0.f;
#pragma unroll
        for (int sp = 0; sp < JSPLIT; sp++) v += g_part[(size_t)sp * (NPOS * COUT) + i];
        g_out[i] = v;
        s += v;
        q += v * v;
    }
    ss[tid] = s; sq[tid] = q;
    __syncthreads();
    if (tid < 32) {
        for (int w = 1; w < 8; w++) { s += ss[w * 32 + tid]; q += sq[w * 32 + tid]; }
        atomicAdd(&g_S[tid], s);
        atomicAdd(&g_S[32 + tid], q);
    }
}

// Stage 3b: normalize (b_skip cancels: constant per-channel shift)
__global__ void k_norm(const float* __restrict__ gamma, const float* __restrict__ beta,
                       float* __restrict__ out) {
    int idx = blockIdx.x * blockDim.x + threadIdx.x;
    if (idx >= NPOS * COUT) return;
    int o = idx & 31;
    float mean = g_S[o] * (1.f / NPOS);
    float var = g_S[32 + o] * (1.f / NPOS) - mean * mean;
    out[idx] = gamma[o] * (g_out[idx] - mean) * rsqrtf(var + EPSV) + beta[o];
}

// ---------------------------------------------------------------------------
extern "C" void kernel_launch(void* const* d_in, const int* in_sizes, int n_in,
                              void* d_out, int out_size) {
    const float* times = (const float*)d_in[0];
    const float* feat  = (const float*)d_in[1];
    const unsigned char* npm = (const unsigned char*)d_in[2];
    const float* W1    = (const float*)d_in[3];
    const float* b1    = (const float*)d_in[4];
    const float* W2    = (const float*)d_in[5];
    const float* b2    = (const float*)d_in[6];
    const float* Wskip = (const float*)d_in[7];
    /* d_in[8] = b_skip: mathematically cancels in layernorm */
    const float* gamma = (const float*)d_in[9];
    const float* beta  = (const float*)d_in[10];

    k_init<<<1, 64>>>();
    k_prep<<<(JDIM * COUT + 255) / 256, 256>>>(W2, b2, Wskip);
    k_stage1<<<NPOS / 8, 256>>>(times, feat, npm, W1, b1);
    dim3 g2(NPOS / PTILE, JSPLIT);
    k_stage2<<<g2, 128>>>();
    k_stats<<<64, 256>>>();
    k_norm<<<(NPOS * COUT + 255) / 256, 256>>>(gamma, beta, (float*)d_out);
}

// round 10
// speedup vs baseline: 1.6365x; 1.0376x over previous
#include <cuda_runtime.h>
#include <cstdint>

typedef unsigned long long ull;

#define BS   4
#define LSEQ 2048
#define CIN  32
#define COUT 32
#define HID  64
#define KTAPS 8
#define NPOS (BS*LSEQ)      /* 8192 */
#define JDIM 2112           /* 2048 outer + 32 fsum + 32 feat */
#define EPSV 1e-5f

#define PTILE 128
#define JSPLIT 11
#define JCH 192             /* JDIM / JSPLIT */
#define JCHUNK 32
#define NCHUNK (JCH / JCHUNK)   /* 6 */
#define ZPAD 36                 /* 16B-aligned rows for cp.async */

// Scratch (no allocations allowed)
__device__ float g_Z[(size_t)NPOS * JDIM];              // 69.2 MB
__device__ float g_Wv[JDIM * COUT];                     // 270 KB
__device__ float g_part[(size_t)JSPLIT * NPOS * COUT];  // 11.5 MB partials
__device__ float g_out[NPOS * COUT];                    // 1 MB (pre-norm)
__device__ float g_S[64];                               // channel sum / sumsq

// ---- packed fp32 helpers (sm_103a f32x2 pipe) ------------------------------
__device__ __forceinline__ ull pk(float lo, float hi) {
    ull r; asm("mov.b64 %0, {%1, %2};" : "=l"(r) : "f"(lo), "f"(hi)); return r;
}
__device__ __forceinline__ void upk(ull v, float& lo, float& hi) {
    asm("mov.b64 {%0, %1}, %2;" : "=f"(lo), "=f"(hi) : "l"(v));
}
__device__ __forceinline__ void fma2(ull& d, ull a, ull b) {
    asm("fma.rn.f32x2 %0, %1, %2, %0;" : "+l"(d) : "l"(a), "l"(b));
}
__device__ __forceinline__ void cpasync16(void* smem_dst, const void* gsrc) {
    unsigned s = (unsigned)__cvta_generic_to_shared(smem_dst);
    asm volatile("cp.async.ca.shared.global [%0], [%1], 16;" :: "r"(s), "l"(gsrc));
}

// ---------------------------------------------------------------------------
// Repack weights: Wv[j][o]  (also zeroes g_S)
//   j in [0,2048):  j = c*64+h  ->  W2[h, c*32+o]
//   j in [2048,2080): c = j-2048 -> b2[c*32+o]
//   j in [2080,2112): c = j-2080 -> W_skip[c][o]
__global__ void k_prep(const float* __restrict__ W2, const float* __restrict__ b2,
                       const float* __restrict__ Wskip) {
    int idx = blockIdx.x * blockDim.x + threadIdx.x;
    if (idx < 64) g_S[idx] = 0.f;
    if (idx >= JDIM * COUT) return;
    int j = idx >> 5, o = idx & 31;
    float v;
    if (j < 2048) {
        int c = j >> 6, h = j & 63;
        v = W2[h * (CIN * COUT) + c * COUT + o];
    } else if (j < 2080) {
        int c = j - 2048;
        v = b2[c * COUT + o];
    } else {
        int c = j - 2080;
        v = Wskip[c * COUT + o];
    }
    g_Wv[idx] = v;
}

// ---------------------------------------------------------------------------
// Stage 1: one warp per (b,t) position. Lane = input channel c (and h-pair).
// Builds Z[pos, c*64+h] = sum_k h[k][h] * f[k][c], plus fsum and raw feat cols.
// Branch-free tap loop: invalid taps are killed exactly via f=0.
__global__ __launch_bounds__(256) void k_stage1(const float* __restrict__ times,
                                                const float* __restrict__ feat,
                                                const unsigned char* __restrict__ npm,
                                                const float* __restrict__ W1,
                                                const float* __restrict__ b1) {
    __shared__ ull W1p[CIN * 32];   // [c][j] = (W1[c][j], W1[c][j+32])
    __shared__ float b1s[HID];
    int tid = threadIdx.x;
    for (int i = tid; i < CIN * 32; i += 256) {
        int c = i >> 5, j = i & 31;
        W1p[i] = pk(W1[c * HID + j], W1[c * HID + 32 + j]);
    }
    if (tid < HID) b1s[tid] = b1[tid];
    __syncthreads();

    int lane = tid & 31;
    int pos = blockIdx.x * 8 + (tid >> 5);
    int b = pos >> 11, t = pos & (LSEQ - 1);

    // mask dtype detection: element 1 is always true (lengths >= 1024).
    bool u8 = (npm[1] != 0);
    const int* npm32 = (const int*)npm;

    ull z2[CIN];                     // (z0[c], z1[c]) packed
#pragma unroll
    for (int c = 0; c < CIN; c++) z2[c] = 0ull;
    float fs = 0.f;

    // inv POS_VEC: 10000^(-(lane/2)/16) ; log2(10000)/16 = 0.83048202...
    float invp = exp2f(-(float)(lane >> 1) * 0.8304820237218407f);
    ull b1p = pk(b1s[lane], b1s[lane + 32]);

    bool mt = u8 ? (npm[b * LSEQ + t] != 0) : (npm32[b * LSEQ + t] != 0);
    float tt = times[b * LSEQ + t];

    if (mt) {
#pragma unroll 2
        for (int k = 0; k < KTAPS; k++) {
            int idx = t - (KTAPS - 1) + k;
            int idxc = idx < 0 ? 0 : idx;
            bool mk = (idx >= 0) &&
                      (u8 ? (npm[b * LSEQ + idxc] != 0) : (npm32[b * LSEQ + idxc] != 0));
            float f = feat[(size_t)(b * LSEQ + idxc) * CIN + lane];
            if (!mk) f = 0.f;                 // exact kill of invalid taps
            fs += f;
            float dt = tt - times[b * LSEQ + idxc];
            float r = dt * invp;
            float te = (lane & 1) ? __cosf(r) : __sinf(r);
            // h-pair GEMV, 2-way split accumulator chains
            ull ap0 = b1p, ap1 = 0ull;
#pragma unroll
            for (int c = 0; c < CIN; c += 2) {
                float tv0 = __shfl_sync(0xffffffffu, te, c);
                float tv1 = __shfl_sync(0xffffffffu, te, c + 1);
                fma2(ap0, pk(tv0, tv0), W1p[c * 32 + lane]);
                fma2(ap1, pk(tv1, tv1), W1p[(c + 1) * 32 + lane]);
            }
            float a0l, a0h, a1l, a1h;
            upk(ap0, a0l, a0h);
            upk(ap1, a1l, a1h);
            float a0 = fmaxf(a0l + a1l, 0.f);
            float a1 = fmaxf(a0h + a1h, 0.f);
            ull a2 = pk(a0, a1);
            // rank-1 accumulate: (z0[c],z1[c]) += (a0,a1)*(f_c,f_c)
#pragma unroll
            for (int c = 0; c < CIN; c++) {
                float fv = __shfl_sync(0xffffffffu, f, c);
                fma2(z2[c], a2, pk(fv, fv));
            }
        }
    }

    float* zr = g_Z + (size_t)pos * JDIM;
#pragma unroll
    for (int c = 0; c < CIN; c++) {
        float z0, z1;
        upk(z2[c], z0, z1);
        zr[c * 64 + lane]      = z0;   // coalesced across lanes
        zr[c * 64 + 32 + lane] = z1;
    }
    zr[2048 + lane] = fs;
    zr[2080 + lane] = feat[(size_t)(b * LSEQ + t) * CIN + lane];
}

// ---------------------------------------------------------------------------
// Stage 2: GEMM partials  g_part[s][8192,32] = Z[8192, jrange_s] @ Wv[jrange_s, 32]
// CTA: 128 pos x 32 outs, 128 threads, 4 pos x 8 out tile via f32x2.
// cp.async double-buffered smem (no register staging). Z read as LDS.128 over x.
__global__ __launch_bounds__(128) void k_stage2() {
    __shared__ __align__(16) float Zs[2][PTILE * ZPAD];   // 2 x 18 KB
    __shared__ __align__(16) float Ws[2][JCHUNK * 32];    // 2 x 4 KB
    int tid = threadIdx.x;
    int og = tid & 3, tp = tid >> 2;
    int ob = og * 8;
    int posBase = blockIdx.x * PTILE;
    int jBase = blockIdx.y * JCH;

    ull acc2[4][4];
#pragma unroll
    for (int i = 0; i < 4; i++)
#pragma unroll
        for (int p = 0; p < 4; p++) acc2[i][p] = 0ull;

    auto issue = [&](int q, int buf) {
        int j0 = jBase + q * JCHUNK;
#pragma unroll
        for (int t2 = 0; t2 < 8; t2++) {
            int idx = t2 * 128 + tid;
            int row = idx >> 3, qd = idx & 7;
            cpasync16(&Zs[buf][row * ZPAD + qd * 4],
                      g_Z + (size_t)(posBase + row) * JDIM + j0 + qd * 4);
        }
#pragma unroll
        for (int t2 = 0; t2 < 2; t2++) {
            cpasync16(&Ws[buf][(t2 * 128 + tid) * 4],
                      g_Wv + j0 * 32 + (t2 * 128 + tid) * 4);
        }
        asm volatile("cp.async.commit_group;");
    };

    issue(0, 0);
    issue(1, 1);
#pragma unroll 1
    for (int q = 0; q < NCHUNK; q++) {
        int bsel = q & 1;
        if (q < NCHUNK - 2) asm volatile("cp.async.wait_group 1;" ::: "memory");
        else                asm volatile("cp.async.wait_group 0;" ::: "memory");
        __syncthreads();
        const float* Zb = Zs[bsel];
        const float* Wb = Ws[bsel];
#pragma unroll
        for (int xq = 0; xq < JCHUNK / 4; xq++) {
            float4 zq[4];
#pragma unroll
            for (int i = 0; i < 4; i++)
                zq[i] = *(const float4*)(Zb + (tp * 4 + i) * ZPAD + xq * 4);
#pragma unroll
            for (int e = 0; e < 4; e++) {
                int x = xq * 4 + e;
                ull w0 = *(const ull*)(Wb + x * 32 + ob);
                ull w1 = *(const ull*)(Wb + x * 32 + ob + 2);
                ull w2 = *(const ull*)(Wb + x * 32 + ob + 4);
                ull w3 = *(const ull*)(Wb + x * 32 + ob + 6);
#pragma unroll
                for (int i = 0; i < 4; i++) {
                    float z = ((const float*)&zq[i])[e];
                    ull zp = pk(z, z);
                    fma2(acc2[i][0], zp, w0);
                    fma2(acc2[i][1], zp, w1);
                    fma2(acc2[i][2], zp, w2);
                    fma2(acc2[i][3], zp, w3);
                }
            }
        }
        __syncthreads();
        if (q + 2 < NCHUNK) issue(q + 2, bsel);
    }

    float* dst = g_part + (size_t)blockIdx.y * (NPOS * COUT);
#pragma unroll
    for (int i = 0; i < 4; i++) {
        int p = posBase + tp * 4 + i;
        float a, b, c, d, e, f, g, h;
        upk(acc2[i][0], a, b); upk(acc2[i][1], c, d);
        upk(acc2[i][2], e, f); upk(acc2[i][3], g, h);
        *(float4*)(dst + p * 32 + ob)     = make_float4(a, b, c, d);
        *(float4*)(dst + p * 32 + ob + 4) = make_float4(e, f, g, h);
    }
}

// ---------------------------------------------------------------------------
// Stage 3a: reduce JSPLIT partials -> g_out, and per-channel sum / sumsq
__global__ __launch_bounds__(256) void k_stats() {
    __shared__ float ss[256], sq[256];
    int tid = threadIdx.x;
    int base = blockIdx.x * 4096;
    float s = 0.f, q = 0.f;
    for (int i = base + tid; i < base + 4096; i += 256) {
        float v = 0.f;
#pragma unroll
        for (int sp = 0; sp < JSPLIT; sp++) v += g_part[(size_t)sp * (NPOS * COUT) + i];
        g_out[i] = v;
        s += v;
        q += v * v;
    }
    ss[tid] = s; sq[tid] = q;
    __syncthreads();
    if (tid < 32) {
        for (int w = 1; w < 8; w++) { s += ss[w * 32 + tid]; q += sq[w * 32 + tid]; }
        atomicAdd(&g_S[tid], s);
        atomicAdd(&g_S[32 + tid], q);
    }
}

// Stage 3b: normalize (b_skip cancels: constant per-channel shift)
__global__ void k_norm(const float* __restrict__ gamma, const float* __restrict__ beta,
                       float* __restrict__ out) {
    int idx = blockIdx.x * blockDim.x + threadIdx.x;
    if (idx >= NPOS * COUT) return;
    int o = idx & 31;
    float mean = g_S[o] * (1.f / NPOS);
    float var = g_S[32 + o] * (1.f / NPOS) - mean * mean;
    out[idx] = gamma[o] * (g_out[idx] - mean) * rsqrtf(var + EPSV) + beta[o];
}

// ---------------------------------------------------------------------------
extern "C" void kernel_launch(void* const* d_in, const int* in_sizes, int n_in,
                              void* d_out, int out_size) {
    const float* times = (const float*)d_in[0];
    const float* feat  = (const float*)d_in[1];
    const unsigned char* npm = (const unsigned char*)d_in[2];
    const float* W1    = (const float*)d_in[3];
    const float* b1    = (const float*)d_in[4];
    const float* W2    = (const float*)d_in[5];
    const float* b2    = (const float*)d_in[6];
    const float* Wskip = (const float*)d_in[7];
    /* d_in[8] = b_skip: mathematically cancels in layernorm */
    const float* gamma = (const float*)d_in[9];
    const float* beta  = (const float*)d_in[10];

    k_prep<<<(JDIM * COUT + 255) / 256, 256>>>(W2, b2, Wskip);
    k_stage1<<<NPOS / 8, 256>>>(times, feat, npm, W1, b1);
    dim3 g2(NPOS / PTILE, JSPLIT);
    k_stage2<<<g2, 128>>>();
    k_stats<<<64, 256>>>();
    k_norm<<<(NPOS * COUT + 255) / 256, 256>>>(gamma, beta, (float*)d_out);
}

// round 11
// speedup vs baseline: 1.6964x; 1.0367x over previous
#include <cuda_runtime.h>
#include <cstdint>

typedef unsigned long long ull;

#define BS   4
#define LSEQ 2048
#define CIN  32
#define COUT 32
#define HID  64
#define KTAPS 8
#define NPOS (BS*LSEQ)      /* 8192 */
#define JDIM 2112           /* 2048 outer + 32 fsum + 32 feat */
#define EPSV 1e-5f

#define PTILE 128
#define JSPLIT 11
#define JCH 192             /* JDIM / JSPLIT */
#define JCHUNK 32
#define NCHUNK (JCH / JCHUNK)   /* 6 */
#define ZPAD 36                 /* 16B-aligned rows for cp.async */

// Scratch (no allocations allowed)
__device__ float g_Z[(size_t)NPOS * JDIM];              // 69.2 MB
__device__ float g_Wv[JDIM * COUT];                     // 270 KB
__device__ float g_part[(size_t)JSPLIT * NPOS * COUT];  // 11.5 MB partials
__device__ float g_out[NPOS * COUT];                    // 1 MB (pre-norm)
__device__ float g_S[64];                               // channel sum / sumsq

// ---- packed fp32 helpers (sm_103a f32x2 pipe) ------------------------------
__device__ __forceinline__ ull pk(float lo, float hi) {
    ull r; asm("mov.b64 %0, {%1, %2};" : "=l"(r) : "f"(lo), "f"(hi)); return r;
}
__device__ __forceinline__ void upk(ull v, float& lo, float& hi) {
    asm("mov.b64 {%0, %1}, %2;" : "=f"(lo), "=f"(hi) : "l"(v));
}
__device__ __forceinline__ void fma2(ull& d, ull a, ull b) {
    asm("fma.rn.f32x2 %0, %1, %2, %0;" : "+l"(d) : "l"(a), "l"(b));
}
__device__ __forceinline__ void cpasync16(void* smem_dst, const void* gsrc) {
    unsigned s = (unsigned)__cvta_generic_to_shared(smem_dst);
    asm volatile("cp.async.ca.shared.global [%0], [%1], 16;" :: "r"(s), "l"(gsrc));
}

// ---------------------------------------------------------------------------
// Repack weights: Wv[j][o]  (also zeroes g_S)
__global__ void k_prep(const float* __restrict__ W2, const float* __restrict__ b2,
                       const float* __restrict__ Wskip) {
    int idx = blockIdx.x * blockDim.x + threadIdx.x;
    if (idx < 64) g_S[idx] = 0.f;
    if (idx >= JDIM * COUT) return;
    int j = idx >> 5, o = idx & 31;
    float v;
    if (j < 2048) {
        int c = j >> 6, h = j & 63;
        v = W2[h * (CIN * COUT) + c * COUT + o];
    } else if (j < 2080) {
        int c = j - 2048;
        v = b2[c * COUT + o];
    } else {
        int c = j - 2080;
        v = Wskip[c * COUT + o];
    }
    g_Wv[idx] = v;
}

// ---------------------------------------------------------------------------
// Stage 1: one warp per (b,t) position. Lane = input channel c (and h-pair).
__global__ __launch_bounds__(256) void k_stage1(const float* __restrict__ times,
                                                const float* __restrict__ feat,
                                                const unsigned char* __restrict__ npm,
                                                const float* __restrict__ W1,
                                                const float* __restrict__ b1) {
    __shared__ ull W1p[CIN * 32];   // [c][j] = (W1[c][j], W1[c][j+32])
    __shared__ float b1s[HID];
    int tid = threadIdx.x;
    for (int i = tid; i < CIN * 32; i += 256) {
        int c = i >> 5, j = i & 31;
        W1p[i] = pk(W1[c * HID + j], W1[c * HID + 32 + j]);
    }
    if (tid < HID) b1s[tid] = b1[tid];
    __syncthreads();

    int lane = tid & 31;
    int pos = blockIdx.x * 8 + (tid >> 5);
    int b = pos >> 11, t = pos & (LSEQ - 1);

    // mask dtype detection: element 1 is always true (lengths >= 1024).
    bool u8 = (npm[1] != 0);
    const int* npm32 = (const int*)npm;

    ull z2[CIN];                     // (z0[c], z1[c]) packed
#pragma unroll
    for (int c = 0; c < CIN; c++) z2[c] = 0ull;
    float fs = 0.f;

    float invp = exp2f(-(float)(lane >> 1) * 0.8304820237218407f);
    ull b1p = pk(b1s[lane], b1s[lane + 32]);

    bool mt = u8 ? (npm[b * LSEQ + t] != 0) : (npm32[b * LSEQ + t] != 0);
    float tt = times[b * LSEQ + t];

    if (mt) {
#pragma unroll 2
        for (int k = 0; k < KTAPS; k++) {
            int idx = t - (KTAPS - 1) + k;
            int idxc = idx < 0 ? 0 : idx;
            bool mk = (idx >= 0) &&
                      (u8 ? (npm[b * LSEQ + idxc] != 0) : (npm32[b * LSEQ + idxc] != 0));
            float f = feat[(size_t)(b * LSEQ + idxc) * CIN + lane];
            if (!mk) f = 0.f;                 // exact kill of invalid taps
            fs += f;
            float dt = tt - times[b * LSEQ + idxc];
            float r = dt * invp;
            float te = (lane & 1) ? __cosf(r) : __sinf(r);
            ull ap0 = b1p, ap1 = 0ull;
#pragma unroll
            for (int c = 0; c < CIN; c += 2) {
                float tv0 = __shfl_sync(0xffffffffu, te, c);
                float tv1 = __shfl_sync(0xffffffffu, te, c + 1);
                fma2(ap0, pk(tv0, tv0), W1p[c * 32 + lane]);
                fma2(ap1, pk(tv1, tv1), W1p[(c + 1) * 32 + lane]);
            }
            float a0l, a0h, a1l, a1h;
            upk(ap0, a0l, a0h);
            upk(ap1, a1l, a1h);
            float a0 = fmaxf(a0l + a1l, 0.f);
            float a1 = fmaxf(a0h + a1h, 0.f);
            ull a2 = pk(a0, a1);
#pragma unroll
            for (int c = 0; c < CIN; c++) {
                float fv = __shfl_sync(0xffffffffu, f, c);
                fma2(z2[c], a2, pk(fv, fv));
            }
        }
    }

    float* zr = g_Z + (size_t)pos * JDIM;
#pragma unroll
    for (int c = 0; c < CIN; c++) {
        float z0, z1;
        upk(z2[c], z0, z1);
        zr[c * 64 + lane]      = z0;   // coalesced across lanes
        zr[c * 64 + 32 + lane] = z1;
    }
    zr[2048 + lane] = fs;
    zr[2080 + lane] = feat[(size_t)(b * LSEQ + t) * CIN + lane];
}

// ---------------------------------------------------------------------------
// Stage 2: GEMM partials  g_part[s][8192,32] = Z[8192, jrange_s] @ Wv[jrange_s, 32]
// cp.async double-buffered smem. Z read as LDS.128 over x.
__global__ __launch_bounds__(128) void k_stage2() {
    __shared__ __align__(16) float Zs[2][PTILE * ZPAD];   // 2 x 18 KB
    __shared__ __align__(16) float Ws[2][JCHUNK * 32];    // 2 x 4 KB
    int tid = threadIdx.x;
    int og = tid & 3, tp = tid >> 2;
    int ob = og * 8;
    int posBase = blockIdx.x * PTILE;
    int jBase = blockIdx.y * JCH;

    ull acc2[4][4];
#pragma unroll
    for (int i = 0; i < 4; i++)
#pragma unroll
        for (int p = 0; p < 4; p++) acc2[i][p] = 0ull;

    auto issue = [&](int q, int buf) {
        int j0 = jBase + q * JCHUNK;
#pragma unroll
        for (int t2 = 0; t2 < 8; t2++) {
            int idx = t2 * 128 + tid;
            int row = idx >> 3, qd = idx & 7;
            cpasync16(&Zs[buf][row * ZPAD + qd * 4],
                      g_Z + (size_t)(posBase + row) * JDIM + j0 + qd * 4);
        }
#pragma unroll
        for (int t2 = 0; t2 < 2; t2++) {
            cpasync16(&Ws[buf][(t2 * 128 + tid) * 4],
                      g_Wv + j0 * 32 + (t2 * 128 + tid) * 4);
        }
        asm volatile("cp.async.commit_group;");
    };

    issue(0, 0);
    issue(1, 1);
#pragma unroll 1
    for (int q = 0; q < NCHUNK; q++) {
        int bsel = q & 1;
        if (q < NCHUNK - 2) asm volatile("cp.async.wait_group 1;" ::: "memory");
        else                asm volatile("cp.async.wait_group 0;" ::: "memory");
        __syncthreads();
        const float* Zb = Zs[bsel];
        const float* Wb = Ws[bsel];
#pragma unroll
        for (int xq = 0; xq < JCHUNK / 4; xq++) {
            float4 zq[4];
#pragma unroll
            for (int i = 0; i < 4; i++)
                zq[i] = *(const float4*)(Zb + (tp * 4 + i) * ZPAD + xq * 4);
#pragma unroll
            for (int e = 0; e < 4; e++) {
                int x = xq * 4 + e;
                ull w0 = *(const ull*)(Wb + x * 32 + ob);
                ull w1 = *(const ull*)(Wb + x * 32 + ob + 2);
                ull w2 = *(const ull*)(Wb + x * 32 + ob + 4);
                ull w3 = *(const ull*)(Wb + x * 32 + ob + 6);
#pragma unroll
                for (int i = 0; i < 4; i++) {
                    float z = ((const float*)&zq[i])[e];
                    ull zp = pk(z, z);
                    fma2(acc2[i][0], zp, w0);
                    fma2(acc2[i][1], zp, w1);
                    fma2(acc2[i][2], zp, w2);
                    fma2(acc2[i][3], zp, w3);
                }
            }
        }
        __syncthreads();
        if (q + 2 < NCHUNK) issue(q + 2, bsel);
    }

    float* dst = g_part + (size_t)blockIdx.y * (NPOS * COUT);
#pragma unroll
    for (int i = 0; i < 4; i++) {
        int p = posBase + tp * 4 + i;
        float a, b, c, d, e, f, g, h;
        upk(acc2[i][0], a, b); upk(acc2[i][1], c, d);
        upk(acc2[i][2], e, f); upk(acc2[i][3], g, h);
        *(float4*)(dst + p * 32 + ob)     = make_float4(a, b, c, d);
        *(float4*)(dst + p * 32 + ob + 4) = make_float4(e, f, g, h);
    }
}

// ---------------------------------------------------------------------------
// Stage 3a: reduce JSPLIT partials -> g_out (float4), per-channel sum/sumsq.
// 256 CTAs x 256 thr; thread i owns float4 #(blk*256+tid) -> channels 4*tid..+3 mod 32
// (block stride 1024 floats == 0 mod 32, so channel set is per-thread constant).
__global__ __launch_bounds__(256) void k_stats() {
    int tid = threadIdx.x;
    int i4 = blockIdx.x * 256 + tid;            // float4 index, 65536 total
    const float4* src = (const float4*)g_part;
    float4 v = src[i4];
#pragma unroll
    for (int sp = 1; sp < JSPLIT; sp++) {
        float4 p = src[(size_t)sp * (NPOS * COUT / 4) + i4];
        v.x += p.x; v.y += p.y; v.z += p.z; v.w += p.w;
    }
    ((float4*)g_out)[i4] = v;

    float s[4] = {v.x, v.y, v.z, v.w};
    float q[4] = {v.x * v.x, v.y * v.y, v.z * v.z, v.w * v.w};
    // lanes l, l+8, l+16, l+24 share the same channel set (4*tid mod 32)
#pragma unroll
    for (int e = 0; e < 4; e++) {
#pragma unroll
        for (int d = 8; d < 32; d <<= 1) {
            s[e] += __shfl_xor_sync(0xffffffffu, s[e], d);
            q[e] += __shfl_xor_sync(0xffffffffu, q[e], d);
        }
    }
    __shared__ float shS[32], shQ[32];
    if (tid < 32) { shS[tid] = 0.f; shQ[tid] = 0.f; }
    __syncthreads();
    int lane = tid & 31;
    if (lane < 8) {
        int c0 = (4 * tid) & 31;   // == 4*lane mod 32, but use tid form for clarity
#pragma unroll
        for (int e = 0; e < 4; e++) {
            atomicAdd(&shS[(c0 + e) & 31], s[e]);
            atomicAdd(&shQ[(c0 + e) & 31], q[e]);
        }
    }
    __syncthreads();
    if (tid < 32) {
        atomicAdd(&g_S[tid], shS[tid]);
        atomicAdd(&g_S[32 + tid], shQ[tid]);
    }
}

// Stage 3b: normalize, float4 (b_skip cancels: constant per-channel shift)
__global__ __launch_bounds__(256) void k_norm(const float* __restrict__ gamma,
                                              const float* __restrict__ beta,
                                              float* __restrict__ out) {
    __shared__ float sc[32], sh[32];   // scale, shift per channel
    int tid = threadIdx.x;
    if (tid < 32) {
        float mean = g_S[tid] * (1.f / NPOS);
        float var = g_S[32 + tid] * (1.f / NPOS) - mean * mean;
        float g = gamma[tid] * rsqrtf(var + EPSV);
        sc[tid] = g;
        sh[tid] = beta[tid] - mean * g;
    }
    __syncthreads();
    int i4 = blockIdx.x * 256 + tid;            // 65536 float4s over 256 blocks
    float4 v = ((const float4*)g_out)[i4];
    int c0 = (4 * tid) & 31;
    v.x = v.x * sc[c0]           + sh[c0];
    v.y = v.y * sc[(c0 + 1) & 31] + sh[(c0 + 1) & 31];
    v.z = v.z * sc[(c0 + 2) & 31] + sh[(c0 + 2) & 31];
    v.w = v.w * sc[(c0 + 3) & 31] + sh[(c0 + 3) & 31];
    ((float4*)out)[i4] = v;
}

// ---------------------------------------------------------------------------
extern "C" void kernel_launch(void* const* d_in, const int* in_sizes, int n_in,
                              void* d_out, int out_size) {
    const float* times = (const float*)d_in[0];
    const float* feat  = (const float*)d_in[1];
    const unsigned char* npm = (const unsigned char*)d_in[2];
    const float* W1    = (const float*)d_in[3];
    const float* b1    = (const float*)d_in[4];
    const float* W2    = (const float*)d_in[5];
    const float* b2    = (const float*)d_in[6];
    const float* Wskip = (const float*)d_in[7];
    /* d_in[8] = b_skip: mathematically cancels in layernorm */
    const float* gamma = (const float*)d_in[9];
    const float* beta  = (const float*)d_in[10];

    k_prep<<<(JDIM * COUT + 255) / 256, 256>>>(W2, b2, Wskip);
    k_stage1<<<NPOS / 8, 256>>>(times, feat, npm, W1, b1);
    dim3 g2(NPOS / PTILE, JSPLIT);
    k_stage2<<<g2, 128>>>();
    k_stats<<<NPOS * COUT / 4 / 256, 256>>>();
    k_norm<<<NPOS * COUT / 4 / 256, 256>>>(gamma, beta, (float*)d_out);
}

// round 12
// speedup vs baseline: 2.1547x; 1.2701x over previous
#include <cuda_runtime.h>
#include <cstdint>

typedef unsigned long long ull;

#define BS   4
#define LSEQ 2048
#define CIN  32
#define COUT 32
#define HID  64
#define KTAPS 8
#define NPOS (BS*LSEQ)      /* 8192 */
#define JDIM 2112           /* 2048 outer + 32 fsum + 32 feat */
#define EPSV 1e-5f

#define PTILE 128
#define JSPLIT 11
#define JCH 192             /* JDIM / JSPLIT */
#define JCHUNK 32
#define NCHUNK (JCH / JCHUNK)   /* 6 */
#define ZPAD 36                 /* 16B-aligned rows for cp.async */

#define S1_POS 4                /* positions per stage1 CTA (128 threads) */
#define TAILCTAS 256

// Scratch (no allocations allowed)
__device__ float g_Z[(size_t)NPOS * JDIM];              // 69.2 MB
__device__ float g_Wv[JDIM * COUT];                     // 270 KB
__device__ float g_part[(size_t)JSPLIT * NPOS * COUT];  // 11.5 MB partials
__device__ float g_S[64];                               // channel sum / sumsq
__device__ unsigned g_ctr;                              // grid-sync counter

// ---- packed fp32 helpers (sm_103a f32x2 pipe) ------------------------------
__device__ __forceinline__ ull pk(float lo, float hi) {
    ull r; asm("mov.b64 %0, {%1, %2};" : "=l"(r) : "f"(lo), "f"(hi)); return r;
}
__device__ __forceinline__ void upk(ull v, float& lo, float& hi) {
    asm("mov.b64 {%0, %1}, %2;" : "=f"(lo), "=f"(hi) : "l"(v));
}
__device__ __forceinline__ void fma2(ull& d, ull a, ull b) {
    asm("fma.rn.f32x2 %0, %1, %2, %0;" : "+l"(d) : "l"(a), "l"(b));
}
__device__ __forceinline__ void cpasync16(void* smem_dst, const void* gsrc) {
    unsigned s = (unsigned)__cvta_generic_to_shared(smem_dst);
    asm volatile("cp.async.ca.shared.global [%0], [%1], 16;" :: "r"(s), "l"(gsrc));
}

// ---------------------------------------------------------------------------
// Repack weights: Wv[j][o]  (also zeroes g_S and the grid-sync counter)
__global__ void k_prep(const float* __restrict__ W2, const float* __restrict__ b2,
                       const float* __restrict__ Wskip) {
    int idx = blockIdx.x * blockDim.x + threadIdx.x;
    if (idx < 64) g_S[idx] = 0.f;
    if (idx == 64) g_ctr = 0u;
    if (idx >= JDIM * COUT) return;
    int j = idx >> 5, o = idx & 31;
    float v;
    if (j < 2048) {
        int c = j >> 6, h = j & 63;
        v = W2[h * (CIN * COUT) + c * COUT + o];
    } else if (j < 2080) {
        int c = j - 2048;
        v = b2[c * COUT + o];
    } else {
        int c = j - 2080;
        v = Wskip[c * COUT + o];
    }
    g_Wv[idx] = v;
}

// ---------------------------------------------------------------------------
// Stage 1: 4 positions per 128-thread CTA, one warp per position.
// feat rows pre-masked to zero in smem (mask is a row property) -> tap masking
// is exact via f=0. te staged in smem; 8-tap-joint GEMV so W1 is read once.
__global__ __launch_bounds__(128) void k_stage1(const float* __restrict__ times,
                                                const float* __restrict__ feat,
                                                const unsigned char* __restrict__ npm,
                                                const float* __restrict__ W1,
                                                const float* __restrict__ b1) {
    __shared__ __align__(16) ull  W1p[CIN * 32];          // [c][j]=(W1[c][j],W1[c][j+32])
    __shared__ float b1s[HID];
    __shared__ __align__(16) float fsm[S1_POS + 7][32];   // masked feat rows
    __shared__ float tsm[S1_POS + 7];
    __shared__ __align__(16) float tesm[S1_POS][KTAPS][32];

    int tid = threadIdx.x;
    int lane = tid & 31;
    int w = tid >> 5;

    // mask dtype detection: element 1 is always true (lengths >= 1024).
    bool u8 = (npm[1] != 0);
    const int* npm32 = (const int*)npm;

    int pos0 = blockIdx.x * S1_POS;
    int b = pos0 >> 11, tbase = pos0 & (LSEQ - 1);

    for (int i = tid; i < CIN * 32; i += 128) {
        int c = i >> 5, j = i & 31;
        W1p[i] = pk(W1[c * HID + j], W1[c * HID + 32 + j]);
    }
    if (tid < HID) b1s[tid] = b1[tid];
    for (int i = tid; i < (S1_POS + 7) * 32; i += 128) {
        int j = i >> 5, c = i & 31;
        int r = tbase - 7 + j;
        bool ok = (r >= 0) &&
                  (u8 ? (npm[b * LSEQ + r] != 0) : (npm32[b * LSEQ + r] != 0));
        fsm[j][c] = ok ? feat[(size_t)(b * LSEQ + r) * CIN + c] : 0.f;
    }
    if (tid < S1_POS + 7) {
        int r = tbase - 7 + tid;
        tsm[tid] = (r >= 0) ? times[b * LSEQ + r] : 0.f;
    }
    __syncthreads();

    int t = tbase + w;
    bool mt = u8 ? (npm[b * LSEQ + t] != 0) : (npm32[b * LSEQ + t] != 0);
    float tt = tsm[w + 7];
    float invp = exp2f(-(float)(lane >> 1) * 0.8304820237218407f);

    ull z2[CIN];
#pragma unroll
    for (int c = 0; c < CIN; c++) z2[c] = 0ull;
    float fs = 0.f;

    if (mt) {
        // phase A: te for all taps -> smem
#pragma unroll
        for (int k = 0; k < KTAPS; k++) {
            float dt = tt - tsm[w + k];
            float r = dt * invp;
            tesm[w][k][lane] = (lane & 1) ? __cosf(r) : __sinf(r);
        }
        __syncwarp();
        // phase B: joint 8-tap GEMV (W1 read once per position)
        ull b1p = pk(b1s[lane], b1s[lane + 32]);
        ull ap[KTAPS];
#pragma unroll
        for (int k = 0; k < KTAPS; k++) ap[k] = b1p;
#pragma unroll
        for (int c4 = 0; c4 < 8; c4++) {
            float4 te4[KTAPS];
#pragma unroll
            for (int k = 0; k < KTAPS; k++)
                te4[k] = *(const float4*)&tesm[w][k][c4 * 4];
            ull wv[4];
#pragma unroll
            for (int e = 0; e < 4; e++)
                wv[e] = W1p[(c4 * 4 + e) * 32 + lane];
#pragma unroll
            for (int e = 0; e < 4; e++)
#pragma unroll
                for (int k = 0; k < KTAPS; k++) {
                    float tv = ((const float*)&te4[k])[e];
                    fma2(ap[k], pk(tv, tv), wv[e]);
                }
        }
        ull a2[KTAPS];
#pragma unroll
        for (int k = 0; k < KTAPS; k++) {
            float a0, a1;
            upk(ap[k], a0, a1);
            a2[k] = pk(fmaxf(a0, 0.f), fmaxf(a1, 0.f));
        }
        // fs: per-lane channel sum over taps (rows already masked)
#pragma unroll
        for (int k = 0; k < KTAPS; k++) fs += fsm[w + k][lane];
        // phase C: joint rank-1 accumulate via broadcast f4 loads
#pragma unroll
        for (int c4 = 0; c4 < 8; c4++) {
            float4 f4[KTAPS];
#pragma unroll
            for (int k = 0; k < KTAPS; k++)
                f4[k] = *(const float4*)&fsm[w + k][c4 * 4];
#pragma unroll
            for (int e = 0; e < 4; e++)
#pragma unroll
                for (int k = 0; k < KTAPS; k++) {
                    float fv = ((const float*)&f4[k])[e];
                    fma2(z2[c4 * 4 + e], a2[k], pk(fv, fv));
                }
        }
    }

    float* zr = g_Z + (size_t)(pos0 + w) * JDIM;
#pragma unroll
    for (int c = 0; c < CIN; c++) {
        float z0, z1;
        upk(z2[c], z0, z1);
        zr[c * 64 + lane]      = z0;   // coalesced across lanes
        zr[c * 64 + 32 + lane] = z1;
    }
    zr[2048 + lane] = fs;
    zr[2080 + lane] = feat[(size_t)(b * LSEQ + t) * CIN + lane];  // unmasked skip
}

// ---------------------------------------------------------------------------
// Stage 2: GEMM partials  g_part[s][8192,32] = Z[8192, jrange_s] @ Wv[jrange_s, 32]
// cp.async double-buffered smem. Z read as LDS.128 over x. (unchanged)
__global__ __launch_bounds__(128) void k_stage2() {
    __shared__ __align__(16) float Zs[2][PTILE * ZPAD];   // 2 x 18 KB
    __shared__ __align__(16) float Ws[2][JCHUNK * 32];    // 2 x 4 KB
    int tid = threadIdx.x;
    int og = tid & 3, tp = tid >> 2;
    int ob = og * 8;
    int posBase = blockIdx.x * PTILE;
    int jBase = blockIdx.y * JCH;

    ull acc2[4][4];
#pragma unroll
    for (int i = 0; i < 4; i++)
#pragma unroll
        for (int p = 0; p < 4; p++) acc2[i][p] = 0ull;

    auto issue = [&](int q, int buf) {
        int j0 = jBase + q * JCHUNK;
#pragma unroll
        for (int t2 = 0; t2 < 8; t2++) {
            int idx = t2 * 128 + tid;
            int row = idx >> 3, qd = idx & 7;
            cpasync16(&Zs[buf][row * ZPAD + qd * 4],
                      g_Z + (size_t)(posBase + row) * JDIM + j0 + qd * 4);
        }
#pragma unroll
        for (int t2 = 0; t2 < 2; t2++) {
            cpasync16(&Ws[buf][(t2 * 128 + tid) * 4],
                      g_Wv + j0 * 32 + (t2 * 128 + tid) * 4);
        }
        asm volatile("cp.async.commit_group;");
    };

    issue(0, 0);
    issue(1, 1);
#pragma unroll 1
    for (int q = 0; q < NCHUNK; q++) {
        int bsel = q & 1;
        if (q < NCHUNK - 2) asm volatile("cp.async.wait_group 1;" ::: "memory");
        else                asm volatile("cp.async.wait_group 0;" ::: "memory");
        __syncthreads();
        const float* Zb = Zs[bsel];
        const float* Wb = Ws[bsel];
#pragma unroll
        for (int xq = 0; xq < JCHUNK / 4; xq++) {
            float4 zq[4];
#pragma unroll
            for (int i = 0; i < 4; i++)
                zq[i] = *(const float4*)(Zb + (tp * 4 + i) * ZPAD + xq * 4);
#pragma unroll
            for (int e = 0; e < 4; e++) {
                int x = xq * 4 + e;
                ull w0 = *(const ull*)(Wb + x * 32 + ob);
                ull w1 = *(const ull*)(Wb + x * 32 + ob + 2);
                ull w2 = *(const ull*)(Wb + x * 32 + ob + 4);
                ull w3 = *(const ull*)(Wb + x * 32 + ob + 6);
#pragma unroll
                for (int i = 0; i < 4; i++) {
                    float z = ((const float*)&zq[i])[e];
                    ull zp = pk(z, z);
                    fma2(acc2[i][0], zp, w0);
                    fma2(acc2[i][1], zp, w1);
                    fma2(acc2[i][2], zp, w2);
                    fma2(acc2[i][3], zp, w3);
                }
            }
        }
        __syncthreads();
        if (q + 2 < NCHUNK) issue(q + 2, bsel);
    }

    float* dst = g_part + (size_t)blockIdx.y * (NPOS * COUT);
#pragma unroll
    for (int i = 0; i < 4; i++) {
        int p = posBase + tp * 4 + i;
        float a, b, c, d, e, f, g, h;
        upk(acc2[i][0], a, b); upk(acc2[i][1], c, d);
        upk(acc2[i][2], e, f); upk(acc2[i][3], g, h);
        *(float4*)(dst + p * 32 + ob)     = make_float4(a, b, c, d);
        *(float4*)(dst + p * 32 + ob + 4) = make_float4(e, f, g, h);
    }
}

// ---------------------------------------------------------------------------
// Tail: reduce JSPLIT partials (in registers), per-channel stats, grid sync,
// normalize, write d_out. One kernel, no g_out round trip.
__global__ __launch_bounds__(256) void k_tail(const float* __restrict__ gamma,
                                              const float* __restrict__ beta,
                                              float* __restrict__ out) {
    int tid = threadIdx.x;
    int i4 = blockIdx.x * 256 + tid;            // float4 index, 65536 total
    const float4* src = (const float4*)g_part;
    float4 v = src[i4];
#pragma unroll
    for (int sp = 1; sp < JSPLIT; sp++) {
        float4 p = src[(size_t)sp * (NPOS * COUT / 4) + i4];
        v.x += p.x; v.y += p.y; v.z += p.z; v.w += p.w;
    }

    float s[4] = {v.x, v.y, v.z, v.w};
    float q[4] = {v.x * v.x, v.y * v.y, v.z * v.z, v.w * v.w};
    // lanes l, l+8, l+16, l+24 share the same channel set (4*tid mod 32)
#pragma unroll
    for (int e = 0; e < 4; e++) {
#pragma unroll
        for (int d = 8; d < 32; d <<= 1) {
            s[e] += __shfl_xor_sync(0xffffffffu, s[e], d);
            q[e] += __shfl_xor_sync(0xffffffffu, q[e], d);
        }
    }
    __shared__ float shS[32], shQ[32];
    if (tid < 32) { shS[tid] = 0.f; shQ[tid] = 0.f; }
    __syncthreads();
    int lane = tid & 31;
    int c0 = (4 * tid) & 31;
    if (lane < 8) {
#pragma unroll
        for (int e = 0; e < 4; e++) {
            atomicAdd(&shS[(c0 + e) & 31], s[e]);
            atomicAdd(&shQ[(c0 + e) & 31], q[e]);
        }
    }
    __syncthreads();
    if (tid < 32) {
        atomicAdd(&g_S[tid], shS[tid]);
        atomicAdd(&g_S[32 + tid], shQ[tid]);
        __threadfence();
    }
    __syncthreads();
    if (tid == 0) {
        atomicAdd(&g_ctr, 1u);
        while (atomicAdd(&g_ctr, 0u) < TAILCTAS) { }
        __threadfence();
    }
    __syncthreads();

    __shared__ float sc[32], sh[32];
    if (tid < 32) {
        float mean = g_S[tid] * (1.f / NPOS);
        float var = g_S[32 + tid] * (1.f / NPOS) - mean * mean;
        float g = gamma[tid] * rsqrtf(var + EPSV);
        sc[tid] = g;
        sh[tid] = beta[tid] - mean * g;
    }
    __syncthreads();
    v.x = v.x * sc[c0]            + sh[c0];
    v.y = v.y * sc[(c0 + 1) & 31] + sh[(c0 + 1) & 31];
    v.z = v.z * sc[(c0 + 2) & 31] + sh[(c0 + 2) & 31];
    v.w = v.w * sc[(c0 + 3) & 31] + sh[(c0 + 3) & 31];
    ((float4*)out)[i4] = v;
}

// ---------------------------------------------------------------------------
extern "C" void kernel_launch(void* const* d_in, const int* in_sizes, int n_in,
                              void* d_out, int out_size) {
    const float* times = (const float*)d_in[0];
    const float* feat  = (const float*)d_in[1];
    const unsigned char* npm = (const unsigned char*)d_in[2];
    const float* W1    = (const float*)d_in[3];
    const float* b1    = (const float*)d_in[4];
    const float* W2    = (const float*)d_in[5];
    const float* b2    = (const float*)d_in[6];
    const float* Wskip = (const float*)d_in[7];
    /* d_in[8] = b_skip: mathematically cancels in layernorm */
    const float* gamma = (const float*)d_in[9];
    const float* beta  = (const float*)d_in[10];

    k_prep<<<(JDIM * COUT + 255) / 256, 256>>>(W2, b2, Wskip);
    k_stage1<<<NPOS / S1_POS, 128>>>(times, feat, npm, W1, b1);
    dim3 g2(NPOS / PTILE, JSPLIT);
    k_stage2<<<g2, 128>>>();
    k_tail<<<TAILCTAS, 256>>>(gamma, beta, (float*)d_out);
}

// round 14
// speedup vs baseline: 2.3633x; 1.0968x over previous
#include <cuda_runtime.h>
#include <cuda_fp16.h>
#include <cstdint>

typedef unsigned long long ull;

#define BS   4
#define LSEQ 2048
#define CIN  32
#define COUT 32
#define HID  64
#define KTAPS 8
#define NPOS (BS*LSEQ)      /* 8192 */
#define JDIM 2112           /* 2048 outer + 32 fsum + 32 feat */
#define EPSV 1e-5f

#define PTILE 128
#define JSPLIT 11
#define JCH 192             /* JDIM / JSPLIT */
#define JCHUNK 32
#define NCHUNK (JCH / JCHUNK)   /* 6 */
#define ZPAD 36

#define S1_POS 4                /* positions per stage1 CTA (128 threads) */
#define TAILCTAS 256

// Scratch (no allocations allowed)
__device__ __half g_Zh[(size_t)NPOS * JDIM];            // 34.6 MB (fp16 Z)
__device__ float g_Wv[JDIM * COUT];                     // 270 KB
__device__ float g_part[(size_t)JSPLIT * NPOS * COUT];  // 11.5 MB partials
__device__ float g_S[64];                               // channel sum / sumsq
__device__ unsigned g_ctr;                              // grid-sync counter

// ---- packed fp32 helpers (sm_103a f32x2 pipe) ------------------------------
__device__ __forceinline__ ull pk(float lo, float hi) {
    ull r; asm("mov.b64 %0, {%1, %2};" : "=l"(r) : "f"(lo), "f"(hi)); return r;
}
__device__ __forceinline__ void upk(ull v, float& lo, float& hi) {
    asm("mov.b64 {%0, %1}, %2;" : "=f"(lo), "=f"(hi) : "l"(v));
}
__device__ __forceinline__ void fma2(ull& d, ull a, ull b) {
    asm("fma.rn.f32x2 %0, %1, %2, %0;" : "+l"(d) : "l"(a), "l"(b));
}
__device__ __forceinline__ void cpasync16(void* smem_dst, const void* gsrc) {
    unsigned s = (unsigned)__cvta_generic_to_shared(smem_dst);
    asm volatile("cp.async.ca.shared.global [%0], [%1], 16;" :: "r"(s), "l"(gsrc));
}

// ---------------------------------------------------------------------------
// Repack weights: Wv[j'][o]  (also zeroes g_S and the grid-sync counter)
// fp16-Z pairing: for j' in [0,2048): c = j'>>6, r = j'&63, h = (r>>1)+32*(r&1)
//   -> W2[h, c*32+o].  Extras unchanged: [2048,2080)=b2, [2080,2112)=W_skip.
__global__ void k_prep(const float* __restrict__ W2, const float* __restrict__ b2,
                       const float* __restrict__ Wskip) {
    int idx = blockIdx.x * blockDim.x + threadIdx.x;
    if (idx < 64) g_S[idx] = 0.f;
    if (idx == 64) g_ctr = 0u;
    if (idx >= JDIM * COUT) return;
    int j = idx >> 5, o = idx & 31;
    float v;
    if (j < 2048) {
        int c = j >> 6, r = j & 63;
        int h = (r >> 1) + ((r & 1) << 5);
        v = W2[h * (CIN * COUT) + c * COUT + o];
    } else if (j < 2080) {
        int c = j - 2048;
        v = b2[c * COUT + o];
    } else {
        int c = j - 2080;
        v = Wskip[c * COUT + o];
    }
    g_Wv[idx] = v;
}

// ---------------------------------------------------------------------------
// Stage 1: 4 positions per 128-thread CTA, one warp per position.
// Z stored fp16: lane writes half2(z0[c], z1[c]) at uint offset c*32+lane.
__global__ __launch_bounds__(128) void k_stage1(const float* __restrict__ times,
                                                const float* __restrict__ feat,
                                                const unsigned char* __restrict__ npm,
                                                const float* __restrict__ W1,
                                                const float* __restrict__ b1) {
    __shared__ __align__(16) ull  W1p[CIN * 32];          // [c][j]=(W1[c][j],W1[c][j+32])
    __shared__ float b1s[HID];
    __shared__ __align__(16) float fsm[S1_POS + 7][32];   // masked feat rows
    __shared__ float tsm[S1_POS + 7];
    __shared__ __align__(16) float tesm[S1_POS][KTAPS][32];

    int tid = threadIdx.x;
    int lane = tid & 31;
    int w = tid >> 5;

    // mask dtype detection: element 1 is always true (lengths >= 1024).
    bool u8 = (npm[1] != 0);
    const int* npm32 = (const int*)npm;

    int pos0 = blockIdx.x * S1_POS;
    int b = pos0 >> 11, tbase = pos0 & (LSEQ - 1);

    for (int i = tid; i < CIN * 32; i += 128) {
        int c = i >> 5, j = i & 31;
        W1p[i] = pk(W1[c * HID + j], W1[c * HID + 32 + j]);
    }
    if (tid < HID) b1s[tid] = b1[tid];
    for (int i = tid; i < (S1_POS + 7) * 32; i += 128) {
        int j = i >> 5, c = i & 31;
        int r = tbase - 7 + j;
        bool ok = (r >= 0) &&
                  (u8 ? (npm[b * LSEQ + r] != 0) : (npm32[b * LSEQ + r] != 0));
        fsm[j][c] = ok ? feat[(size_t)(b * LSEQ + r) * CIN + c] : 0.f;
    }
    if (tid < S1_POS + 7) {
        int r = tbase - 7 + tid;
        tsm[tid] = (r >= 0) ? times[b * LSEQ + r] : 0.f;
    }
    __syncthreads();

    int t = tbase + w;
    bool mt = u8 ? (npm[b * LSEQ + t] != 0) : (npm32[b * LSEQ + t] != 0);
    float tt = tsm[w + 7];
    float invp = exp2f(-(float)(lane >> 1) * 0.8304820237218407f);

    ull z2[CIN];
#pragma unroll
    for (int c = 0; c < CIN; c++) z2[c] = 0ull;
    float fs = 0.f;

    if (mt) {
        // phase A: te for all taps -> smem
#pragma unroll
        for (int k = 0; k < KTAPS; k++) {
            float dt = tt - tsm[w + k];
            float r = dt * invp;
            tesm[w][k][lane] = (lane & 1) ? __cosf(r) : __sinf(r);
        }
        __syncwarp();
        // phase B: joint 8-tap GEMV (W1 read once per position)
        ull b1p = pk(b1s[lane], b1s[lane + 32]);
        ull ap[KTAPS];
#pragma unroll
        for (int k = 0; k < KTAPS; k++) ap[k] = b1p;
#pragma unroll
        for (int c4 = 0; c4 < 8; c4++) {
            float4 te4[KTAPS];
#pragma unroll
            for (int k = 0; k < KTAPS; k++)
                te4[k] = *(const float4*)&tesm[w][k][c4 * 4];
            ull wv[4];
#pragma unroll
            for (int e = 0; e < 4; e++)
                wv[e] = W1p[(c4 * 4 + e) * 32 + lane];
#pragma unroll
            for (int e = 0; e < 4; e++)
#pragma unroll
                for (int k = 0; k < KTAPS; k++) {
                    float tv = ((const float*)&te4[k])[e];
                    fma2(ap[k], pk(tv, tv), wv[e]);
                }
        }
        ull a2[KTAPS];
#pragma unroll
        for (int k = 0; k < KTAPS; k++) {
            float a0, a1;
            upk(ap[k], a0, a1);
            a2[k] = pk(fmaxf(a0, 0.f), fmaxf(a1, 0.f));
        }
        // fs: per-lane channel sum over taps (rows already masked)
#pragma unroll
        for (int k = 0; k < KTAPS; k++) fs += fsm[w + k][lane];
        // phase C: joint rank-1 accumulate via broadcast f4 loads
#pragma unroll
        for (int c4 = 0; c4 < 8; c4++) {
            float4 f4[KTAPS];
#pragma unroll
            for (int k = 0; k < KTAPS; k++)
                f4[k] = *(const float4*)&fsm[w + k][c4 * 4];
#pragma unroll
            for (int e = 0; e < 4; e++)
#pragma unroll
                for (int k = 0; k < KTAPS; k++) {
                    float fv = ((const float*)&f4[k])[e];
                    fma2(z2[c4 * 4 + e], a2[k], pk(fv, fv));
                }
        }
    }

    __half* zrow = g_Zh + (size_t)(pos0 + w) * JDIM;
    unsigned* zr = (unsigned*)zrow;
#pragma unroll
    for (int c = 0; c < CIN; c++) {
        float z0, z1;
        upk(z2[c], z0, z1);
        __half2 hv = __floats2half2_rn(z0, z1);
        zr[c * 32 + lane] = *(unsigned*)&hv;       // coalesced 128B per c
    }
    zrow[2048 + lane] = __float2half(fs);
    zrow[2080 + lane] = __float2half(feat[(size_t)(b * LSEQ + t) * CIN + lane]);
}

// ---------------------------------------------------------------------------
// Stage 2: GEMM partials  g_part[s][8192,32] = Z[8192, jrange_s] @ Wv[jrange_s, 32]
// Z fp16 in global, staged through registers (LDG.128 of halves) -> fp32 smem.
// Wv via cp.async double buffer. FMA2 inner loop unchanged.
__global__ __launch_bounds__(128) void k_stage2() {
    __shared__ __align__(16) float Zs[2][PTILE * ZPAD];   // 2 x 18 KB fp32
    __shared__ __align__(16) float Ws[2][JCHUNK * 32];    // 2 x 4 KB
    int tid = threadIdx.x;
    int og = tid & 3, tp = tid >> 2;
    int ob = og * 8;
    int posBase = blockIdx.x * PTILE;
    int jBase = blockIdx.y * JCH;

    ull acc2[4][4];
#pragma unroll
    for (int i = 0; i < 4; i++)
#pragma unroll
        for (int p = 0; p < 4; p++) acc2[i][p] = 0ull;

    uint4 vzh[4];   // 4 x 16B = 32 halves staged per thread
    auto ldgZ = [&](int q) {
        int j0 = jBase + q * JCHUNK;
#pragma unroll
        for (int t2 = 0; t2 < 4; t2++) {
            int idx = t2 * 128 + tid;
            int row = idx >> 2, seg = idx & 3;
            vzh[t2] = *(const uint4*)(g_Zh + (size_t)(posBase + row) * JDIM + j0 + seg * 8);
        }
    };
    auto stsZ = [&](int buf) {
#pragma unroll
        for (int t2 = 0; t2 < 4; t2++) {
            int idx = t2 * 128 + tid;
            int row = idx >> 2, seg = idx & 3;
            float* d = Zs[buf] + row * ZPAD + seg * 8;
            const __half2* hp = (const __half2*)&vzh[t2];
            float2 f0 = __half22float2(hp[0]);
            float2 f1 = __half22float2(hp[1]);
            float2 f2 = __half22float2(hp[2]);
            float2 f3 = __half22float2(hp[3]);
            *(float4*)(d)     = make_float4(f0.x, f0.y, f1.x, f1.y);
            *(float4*)(d + 4) = make_float4(f2.x, f2.y, f3.x, f3.y);
        }
    };
    auto wsIssue = [&](int q, int buf) {
        int j0 = jBase + q * JCHUNK;
#pragma unroll
        for (int t2 = 0; t2 < 2; t2++)
            cpasync16(&Ws[buf][(t2 * 128 + tid) * 4],
                      g_Wv + j0 * 32 + (t2 * 128 + tid) * 4);
        asm volatile("cp.async.commit_group;");
    };

    wsIssue(0, 0);
    wsIssue(1, 1);
    ldgZ(0);
    stsZ(0);
    ldgZ(1);                       // in flight during first compute
#pragma unroll 1
    for (int q = 0; q < NCHUNK; q++) {
        int bsel = q & 1;
        if (q < NCHUNK - 1) asm volatile("cp.async.wait_group 1;" ::: "memory");
        else                asm volatile("cp.async.wait_group 0;" ::: "memory");
        __syncthreads();
        const float* Zb = Zs[bsel];
        const float* Wb = Ws[bsel];
#pragma unroll
        for (int xq = 0; xq < JCHUNK / 4; xq++) {
            float4 zq[4];
#pragma unroll
            for (int i = 0; i < 4; i++)
                zq[i] = *(const float4*)(Zb + (tp * 4 + i) * ZPAD + xq * 4);
#pragma unroll
            for (int e = 0; e < 4; e++) {
                int x = xq * 4 + e;
                ull w0 = *(const ull*)(Wb + x * 32 + ob);
                ull w1 = *(const ull*)(Wb + x * 32 + ob + 2);
                ull w2 = *(const ull*)(Wb + x * 32 + ob + 4);
                ull w3 = *(const ull*)(Wb + x * 32 + ob + 6);
#pragma unroll
                for (int i = 0; i < 4; i++) {
                    float z = ((const float*)&zq[i])[e];
                    ull zp = pk(z, z);
                    fma2(acc2[i][0], zp, w0);
                    fma2(acc2[i][1], zp, w1);
                    fma2(acc2[i][2], zp, w2);
                    fma2(acc2[i][3], zp, w3);
                }
            }
        }
        __syncthreads();
        if (q + 1 < NCHUNK) {
            stsZ((q + 1) & 1);                  // regs -> other buffer
            if (q + 2 < NCHUNK) { ldgZ(q + 2); wsIssue(q + 2, bsel); }
        }
    }

    float* dst = g_part + (size_t)blockIdx.y * (NPOS * COUT);
#pragma unroll
    for (int i = 0; i < 4; i++) {
        int p = posBase + tp * 4 + i;
        float a, b, c, d, e, f, g, h;
        upk(acc2[i][0], a, b); upk(acc2[i][1], c, d);
        upk(acc2[i][2], e, f); upk(acc2[i][3], g, h);
        *(float4*)(dst + p * 32 + ob)     = make_float4(a, b, c, d);
        *(float4*)(dst + p * 32 + ob + 4) = make_float4(e, f, g, h);
    }
}

// ---------------------------------------------------------------------------
// Tail: reduce JSPLIT partials (in registers), per-channel stats, grid sync,
// normalize, write d_out. One kernel, no g_out round trip.
__global__ __launch_bounds__(256) void k_tail(const float* __restrict__ gamma,
                                              const float* __restrict__ beta,
                                              float* __restrict__ out) {
    int tid = threadIdx.x;
    int i4 = blockIdx.x * 256 + tid;            // float4 index, 65536 total
    const float4* src = (const float4*)g_part;
    float4 v = src[i4];
#pragma unroll
    for (int sp = 1; sp < JSPLIT; sp++) {
        float4 p = src[(size_t)sp * (NPOS * COUT / 4) + i4];
        v.x += p.x; v.y += p.y; v.z += p.z; v.w += p.w;
    }

    float s[4] = {v.x, v.y, v.z, v.w};
    float q[4] = {v.x * v.x, v.y * v.y, v.z * v.z, v.w * v.w};
    // lanes l, l+8, l+16, l+24 share the same channel set (4*tid mod 32)
#pragma unroll
    for (int e = 0; e < 4; e++) {
#pragma unroll
        for (int d = 8; d < 32; d <<= 1) {
            s[e] += __shfl_xor_sync(0xffffffffu, s[e], d);
            q[e] += __shfl_xor_sync(0xffffffffu, q[e], d);
        }
    }
    __shared__ float shS[32], shQ[32];
    if (tid < 32) { shS[tid] = 0.f; shQ[tid] = 0.f; }
    __syncthreads();
    int lane = tid & 31;
    int c0 = (4 * tid) & 31;
    if (lane < 8) {
#pragma unroll
        for (int e = 0; e < 4; e++) {
            atomicAdd(&shS[(c0 + e) & 31], s[e]);
            atomicAdd(&shQ[(c0 + e) & 31], q[e]);
        }
    }
    __syncthreads();
    if (tid < 32) {
        atomicAdd(&g_S[tid], shS[tid]);
        atomicAdd(&g_S[32 + tid], shQ[tid]);
        __threadfence();
    }
    __syncthreads();
    if (tid == 0) {
        atomicAdd(&g_ctr, 1u);
        while (atomicAdd(&g_ctr, 0u) < TAILCTAS) { }
        __threadfence();
    }
    __syncthreads();

    __shared__ float sc[32], sh[32];
    if (tid < 32) {
        float mean = g_S[tid] * (1.f / NPOS);
        float var = g_S[32 + tid] * (1.f / NPOS) - mean * mean;
        float g = gamma[tid] * rsqrtf(var + EPSV);
        sc[tid] = g;
        sh[tid] = beta[tid] - mean * g;
    }
    __syncthreads();
    v.x = v.x * sc[c0]            + sh[c0];
    v.y = v.y * sc[(c0 + 1) & 31] + sh[(c0 + 1) & 31];
    v.z = v.z * sc[(c0 + 2) & 31] + sh[(c0 + 2) & 31];
    v.w = v.w * sc[(c0 + 3) & 31] + sh[(c0 + 3) & 31];
    ((float4*)out)[i4] = v;
}

// ---------------------------------------------------------------------------
extern "C" void kernel_launch(void* const* d_in, const int* in_sizes, int n_in,
                              void* d_out, int out_size) {
    const float* times = (const float*)d_in[0];
    const float* feat  = (const float*)d_in[1];
    const unsigned char* npm = (const unsigned char*)d_in[2];
    const float* W1    = (const float*)d_in[3];
    const float* b1    = (const float*)d_in[4];
    const float* W2    = (const float*)d_in[5];
    const float* b2    = (const float*)d_in[6];
    const float* Wskip = (const float*)d_in[7];
    /* d_in[8] = b_skip: mathematically cancels in layernorm */
    const float* gamma = (const float*)d_in[9];
    const float* beta  = (const float*)d_in[10];

    k_prep<<<(JDIM * COUT + 255) / 256, 256>>>(W2, b2, Wskip);
    k_stage1<<<NPOS / S1_POS, 128>>>(times, feat, npm, W1, b1);
    dim3 g2(NPOS / PTILE, JSPLIT);
    k_stage2<<<g2, 128>>>();
    k_tail<<<TAILCTAS, 256>>>(gamma, beta, (float*)d_out);
}

// round 16
// speedup vs baseline: 3.9991x; 1.6922x over previous
#include <cuda_runtime.h>
#include <cuda_fp16.h>
#include <cstdint>

typedef unsigned long long ull;

#define BS   4
#define LSEQ 2048
#define CIN  32
#define COUT 32
#define HID  64
#define KTAPS 8
#define NPOS (BS*LSEQ)      /* 8192 */
#define JDIM 2112           /* halves per Z row */
#define NKP  1056           /* half2 pairs per row */
#define EPSV 1e-5f

#define S1_POS 4
#define GCTAS 128           /* k_gemm CTAs: 64 positions each */
#define GTILE 64
#define NCH 11              /* K chunks of 96 pairs */
// dynamic smem carve (bytes)
#define OFF_A 0             /* 2 x 64 x 100 half2 = 51200 */
#define OFF_B 51200         /* 2 x 96 x 32 half2 = 24576 */
#define OFF_D 75776         /* 64 x 34 floats    = 8704  */
#define OFF_S 84480         /* 4 x 32 floats     = 512   */
#define SMEM_TOTAL 84992

// Scratch (no allocations allowed)
__device__ __half g_Zh[(size_t)NPOS * JDIM];            // 34.6 MB (fp16 Z, row-major)
__device__ __align__(16) __half2 g_WvB[NCH * 3072];     // swizzled B chunk images
__device__ float g_S[64];
__device__ unsigned g_ctr;

// ---- helpers ---------------------------------------------------------------
__device__ __forceinline__ ull pk(float lo, float hi) {
    ull r; asm("mov.b64 %0, {%1, %2};" : "=l"(r) : "f"(lo), "f"(hi)); return r;
}
__device__ __forceinline__ void upk(ull v, float& lo, float& hi) {
    asm("mov.b64 {%0, %1}, %2;" : "=f"(lo), "=f"(hi) : "l"(v));
}
__device__ __forceinline__ void fma2(ull& d, ull a, ull b) {
    asm("fma.rn.f32x2 %0, %1, %2, %0;" : "+l"(d) : "l"(a), "l"(b));
}
__device__ __forceinline__ void cpasync16(void* smem_dst, const void* gsrc) {
    unsigned s = (unsigned)__cvta_generic_to_shared(smem_dst);
    asm volatile("cp.async.ca.shared.global [%0], [%1], 16;" :: "r"(s), "l"(gsrc));
}
__device__ __forceinline__ void mma16816(float* c, unsigned a0, unsigned a1,
                                         unsigned a2, unsigned a3,
                                         unsigned b0, unsigned b1) {
    asm volatile("mma.sync.aligned.m16n8k16.row.col.f32.f16.f16.f32 "
        "{%0,%1,%2,%3}, {%4,%5,%6,%7}, {%8,%9}, {%0,%1,%2,%3};"
        : "+f"(c[0]), "+f"(c[1]), "+f"(c[2]), "+f"(c[3])
        : "r"(a0), "r"(a1), "r"(a2), "r"(a3), "r"(b0), "r"(b1));
}

// ---------------------------------------------------------------------------
// k_prep: build swizzled fp16 B chunk images (pair kp = (Wv[2kp], Wv[2kp+1])).
// j' = 2kp mapping (matches stage1 Z pairing, validated in R14):
//   kp<1024: c=kp>>5, h=kp&31 -> lo=W2[h, c*32+o], hi=W2[h+32, c*32+o]
//   kp in [1024,1040): e=2(kp-1024) -> b2[e*32+o], b2[(e+1)*32+o]
//   kp in [1040,1056): e=2(kp-1040) -> W_skip pair
// dst half2 index: ch*3072 + kpl*32 + (o ^ ((kpl&3)<<3))   [XOR bank swizzle]
__global__ void k_prep(const float* __restrict__ W2, const float* __restrict__ b2,
                       const float* __restrict__ Wskip) {
    int idx = blockIdx.x * blockDim.x + threadIdx.x;
    if (idx < 64) g_S[idx] = 0.f;
    if (idx == 64) g_ctr = 0u;
    if (idx >= NKP * 32) return;
    int kp = idx >> 5, o = idx & 31;
    float lo, hi;
    if (kp < 1024) {
        int c = kp >> 5, hl = kp & 31;
        lo = W2[hl * (CIN * COUT) + c * COUT + o];
        hi = W2[(hl + 32) * (CIN * COUT) + c * COUT + o];
    } else if (kp < 1040) {
        int e = 2 * (kp - 1024);
        lo = b2[e * COUT + o];
        hi = b2[(e + 1) * COUT + o];
    } else {
        int e = 2 * (kp - 1040);
        lo = Wskip[e * COUT + o];
        hi = Wskip[(e + 1) * COUT + o];
    }
    int ch = kp / 96, kpl = kp % 96;
    g_WvB[ch * 3072 + kpl * 32 + (o ^ ((kpl & 3) << 3))] = __floats2half2_rn(lo, hi);
}

// ---------------------------------------------------------------------------
// Stage 1 (exact R14 structure): 4 positions per 128-thread CTA, warp/position.
__global__ __launch_bounds__(128) void k_stage1(const float* __restrict__ times,
                                                const float* __restrict__ feat,
                                                const unsigned char* __restrict__ npm,
                                                const float* __restrict__ W1,
                                                const float* __restrict__ b1) {
    __shared__ __align__(16) ull  W1p[CIN * 32];
    __shared__ float b1s[HID];
    __shared__ __align__(16) float fsm[S1_POS + 7][32];
    __shared__ float tsm[S1_POS + 7];
    __shared__ __align__(16) float tesm[S1_POS][KTAPS][32];

    int tid = threadIdx.x;
    int lane = tid & 31;
    int w = tid >> 5;

    bool u8 = (npm[1] != 0);
    const int* npm32 = (const int*)npm;

    int pos0 = blockIdx.x * S1_POS;
    int b = pos0 >> 11, tbase = pos0 & (LSEQ - 1);

    for (int i = tid; i < CIN * 32; i += 128) {
        int c = i >> 5, j = i & 31;
        W1p[i] = pk(W1[c * HID + j], W1[c * HID + 32 + j]);
    }
    if (tid < HID) b1s[tid] = b1[tid];
    for (int i = tid; i < (S1_POS + 7) * 32; i += 128) {
        int j = i >> 5, c = i & 31;
        int r = tbase - 7 + j;
        bool ok = (r >= 0) &&
                  (u8 ? (npm[b * LSEQ + r] != 0) : (npm32[b * LSEQ + r] != 0));
        fsm[j][c] = ok ? feat[(size_t)(b * LSEQ + r) * CIN + c] : 0.f;
    }
    if (tid < S1_POS + 7) {
        int r = tbase - 7 + tid;
        tsm[tid] = (r >= 0) ? times[b * LSEQ + r] : 0.f;
    }
    __syncthreads();

    int t = tbase + w;
    bool mt = u8 ? (npm[b * LSEQ + t] != 0) : (npm32[b * LSEQ + t] != 0);
    float tt = tsm[w + 7];
    float invp = exp2f(-(float)(lane >> 1) * 0.8304820237218407f);

    ull z2[CIN];
#pragma unroll
    for (int c = 0; c < CIN; c++) z2[c] = 0ull;
    float fs = 0.f;

    if (mt) {
#pragma unroll
        for (int k = 0; k < KTAPS; k++) {
            float dt = tt - tsm[w + k];
            float r = dt * invp;
            tesm[w][k][lane] = (lane & 1) ? __cosf(r) : __sinf(r);
        }
        __syncwarp();
        ull b1p = pk(b1s[lane], b1s[lane + 32]);
        ull ap[KTAPS];
#pragma unroll
        for (int k = 0; k < KTAPS; k++) ap[k] = b1p;
#pragma unroll
        for (int c4 = 0; c4 < 8; c4++) {
            float4 te4[KTAPS];
#pragma unroll
            for (int k = 0; k < KTAPS; k++)
                te4[k] = *(const float4*)&tesm[w][k][c4 * 4];
            ull wv[4];
#pragma unroll
            for (int e = 0; e < 4; e++)
                wv[e] = W1p[(c4 * 4 + e) * 32 + lane];
#pragma unroll
            for (int e = 0; e < 4; e++)
#pragma unroll
                for (int k = 0; k < KTAPS; k++) {
                    float tv = ((const float*)&te4[k])[e];
                    fma2(ap[k], pk(tv, tv), wv[e]);
                }
        }
        ull a2[KTAPS];
#pragma unroll
        for (int k = 0; k < KTAPS; k++) {
            float a0, a1;
            upk(ap[k], a0, a1);
            a2[k] = pk(fmaxf(a0, 0.f), fmaxf(a1, 0.f));
        }
#pragma unroll
        for (int k = 0; k < KTAPS; k++) fs += fsm[w + k][lane];
#pragma unroll
        for (int c4 = 0; c4 < 8; c4++) {
            float4 f4[KTAPS];
#pragma unroll
            for (int k = 0; k < KTAPS; k++)
                f4[k] = *(const float4*)&fsm[w + k][c4 * 4];
#pragma unroll
            for (int e = 0; e < 4; e++)
#pragma unroll
                for (int k = 0; k < KTAPS; k++) {
                    float fv = ((const float*)&f4[k])[e];
                    fma2(z2[c4 * 4 + e], a2[k], pk(fv, fv));
                }
        }
    }

    __half* zrow = g_Zh + (size_t)(pos0 + w) * JDIM;
    unsigned* zr = (unsigned*)zrow;
#pragma unroll
    for (int c = 0; c < CIN; c++) {
        float z0, z1;
        upk(z2[c], z0, z1);
        __half2 hv = __floats2half2_rn(z0, z1);
        zr[c * 32 + lane] = *(unsigned*)&hv;
    }
    zrow[2048 + lane] = __float2half(fs);
    zrow[2080 + lane] = __float2half(feat[(size_t)(b * LSEQ + t) * CIN + lane]);
}

// ---------------------------------------------------------------------------
// k_gemm: 64 positions per CTA, full K via HMMA (mma.sync m16n8k16),
// double-buffered cp.async, fused stats + grid-sync + layernorm.
__global__ __launch_bounds__(256) void k_gemm(const float* __restrict__ gamma,
                                              const float* __restrict__ beta,
                                              float* __restrict__ out) {
    extern __shared__ __align__(16) char smem[];
    unsigned* As  = (unsigned*)(smem + OFF_A);   // [buf*6400 + row*100 + kp]
    unsigned* Bsm = (unsigned*)(smem + OFF_B);   // [buf*3072 + kp*32 + o_sw]
    float* Dp  = (float*)(smem + OFF_D);         // [row*34 + col]
    float* shS = (float*)(smem + OFF_S);
    float* shQ = shS + 32;
    float* scv = shQ + 32;
    float* sfv = scv + 32;

    int tid = threadIdx.x;
    int lane = tid & 31;
    int w = tid >> 5;
    int g = lane >> 2, t = lane & 3;
    int mb = w & 3, kh = w >> 2;
    int posBase = blockIdx.x * GTILE;

    if (tid < 32) { shS[tid] = 0.f; shQ[tid] = 0.f; }

    auto fill = [&](int ch, int buf) {
        // A: 64 rows x 192 halves (24 x 16B per row)
#pragma unroll
        for (int i = 0; i < 6; i++) {
            int idx = i * 256 + tid;
            int row = idx / 24, seg = idx % 24;
            cpasync16((char*)(As + buf * 6400 + row * 100 + seg * 4),
                      g_Zh + (size_t)(posBase + row) * JDIM + ch * 192 + seg * 8);
        }
        // B: 12KB contiguous (pre-swizzled image)
#pragma unroll
        for (int i = 0; i < 3; i++) {
            int idx = i * 256 + tid;
            cpasync16((char*)(Bsm + buf * 3072 + idx * 4),
                      (const char*)(g_WvB + ch * 3072) + idx * 16);
        }
        asm volatile("cp.async.commit_group;" ::: "memory");
    };

    float acc[4][4];
#pragma unroll
    for (int nb = 0; nb < 4; nb++)
#pragma unroll
        for (int i = 0; i < 4; i++) acc[nb][i] = 0.f;

    fill(0, 0);
    fill(1, 1);
#pragma unroll 1
    for (int ch = 0; ch < NCH; ch++) {
        int s = ch & 1;
        if (ch < NCH - 2) asm volatile("cp.async.wait_group 1;" ::: "memory");
        else              asm volatile("cp.async.wait_group 0;" ::: "memory");
        __syncthreads();
        const unsigned* Ab = As + s * 6400 + (mb * 16 + g) * 100;
        const unsigned* Bb = Bsm + s * 3072;
#pragma unroll
        for (int kss = 0; kss < 6; kss++) {
            int ks = kh * 6 + kss;
            int kp = ks * 8 + t;
            unsigned a0 = Ab[kp];
            unsigned a1 = Ab[800 + kp];
            unsigned a2 = Ab[kp + 4];
            unsigned a3 = Ab[800 + kp + 4];
#pragma unroll
            for (int nb = 0; nb < 4; nb++) {
                int osw = (nb * 8 + g) ^ (t << 3);
                unsigned b0 = Bb[kp * 32 + osw];
                unsigned b1 = Bb[(kp + 4) * 32 + osw];
                mma16816(acc[nb], a0, a1, a2, a3, b0, b1);
            }
        }
        __syncthreads();
        if (ch + 2 < NCH) fill(ch + 2, s);
    }

    // combine K-halves: warps 4-7 stash, warps 0-3 add
    int r0 = mb * 16 + g;
    if (w >= 4) {
#pragma unroll
        for (int nb = 0; nb < 4; nb++) {
            int c0 = nb * 8 + 2 * t;
            Dp[r0 * 34 + c0]       = acc[nb][0];
            Dp[r0 * 34 + c0 + 1]   = acc[nb][1];
            Dp[(r0+8) * 34 + c0]   = acc[nb][2];
            Dp[(r0+8) * 34 + c0+1] = acc[nb][3];
        }
    }
    __syncthreads();
    if (w < 4) {
#pragma unroll
        for (int nb = 0; nb < 4; nb++) {
            int c0 = nb * 8 + 2 * t;
            acc[nb][0] += Dp[r0 * 34 + c0];
            acc[nb][1] += Dp[r0 * 34 + c0 + 1];
            acc[nb][2] += Dp[(r0+8) * 34 + c0];
            acc[nb][3] += Dp[(r0+8) * 34 + c0 + 1];
        }
    }
    __syncthreads();
    if (w < 4) {
#pragma unroll
        for (int nb = 0; nb < 4; nb++) {
            int c0 = nb * 8 + 2 * t;
            Dp[r0 * 34 + c0]       = acc[nb][0];
            Dp[r0 * 34 + c0 + 1]   = acc[nb][1];
            Dp[(r0+8) * 34 + c0]   = acc[nb][2];
            Dp[(r0+8) * 34 + c0+1] = acc[nb][3];
        }
    }
    __syncthreads();

    // per-channel stats (lanes hit distinct banks/channels)
    {
        int c = tid & 31;
        int rb = tid >> 5;
        float s = 0.f, q = 0.f;
#pragma unroll
        for (int k = 0; k < 8; k++) {
            float v = Dp[(k * 8 + rb) * 34 + c];
            s += v;
            q += v * v;
        }
        atomicAdd(&shS[c], s);
        atomicAdd(&shQ[c], q);
    }
    __syncthreads();
    if (tid < 32) {
        atomicAdd(&g_S[tid], shS[tid]);
        atomicAdd(&g_S[32 + tid], shQ[tid]);
        __threadfence();
    }
    __syncthreads();
    if (tid == 0) {
        atomicAdd(&g_ctr, 1u);
        while (atomicAdd(&g_ctr, 0u) < GCTAS) { }
        __threadfence();
    }
    __syncthreads();
    if (tid < 32) {
        float mean = g_S[tid] * (1.f / NPOS);
        float var = g_S[32 + tid] * (1.f / NPOS) - mean * mean;
        float gm = gamma[tid] * rsqrtf(var + EPSV);
        scv[tid] = gm;
        sfv[tid] = beta[tid] - mean * gm;
    }
    __syncthreads();

#pragma unroll
    for (int it = 0; it < 2; it++) {
        int i = it * 256 + tid;
        int row = i >> 3, c4 = (i & 7) * 4;
        float4 v = make_float4(
            Dp[row * 34 + c4]     * scv[c4]     + sfv[c4],
            Dp[row * 34 + c4 + 1] * scv[c4 + 1] + sfv[c4 + 1],
            Dp[row * 34 + c4 + 2] * scv[c4 + 2] + sfv[c4 + 2],
            Dp[row * 34 + c4 + 3] * scv[c4 + 3] + sfv[c4 + 3]);
        *(float4*)(out + (size_t)(posBase + row) * COUT + c4) = v;
    }
}

// ---------------------------------------------------------------------------
extern "C" void kernel_launch(void* const* d_in, const int* in_sizes, int n_in,
                              void* d_out, int out_size) {
    const float* times = (const float*)d_in[0];
    const float* feat  = (const float*)d_in[1];
    const unsigned char* npm = (const unsigned char*)d_in[2];
    const float* W1    = (const float*)d_in[3];
    const float* b1    = (const float*)d_in[4];
    const float* W2    = (const float*)d_in[5];
    const float* b2    = (const float*)d_in[6];
    const float* Wskip = (const float*)d_in[7];
    /* d_in[8] = b_skip: cancels in layernorm */
    const float* gamma = (const float*)d_in[9];
    const float* beta  = (const float*)d_in[10];

    static bool attr_done = false;
    if (!attr_done) {
        cudaFuncSetAttribute(k_gemm, cudaFuncAttributeMaxDynamicSharedMemorySize,
                             SMEM_TOTAL);
        attr_done = true;
    }

    k_prep<<<(NKP * 32 + 255) / 256, 256>>>(W2, b2, Wskip);
    k_stage1<<<NPOS / S1_POS, 128>>>(times, feat, npm, W1, b1);
    k_gemm<<<GCTAS, 256, SMEM_TOTAL>>>(gamma, beta, (float*)d_out);
}